// round 1
// baseline (speedup 1.0000x reference)
#include <cuda_runtime.h>
#include <cuda_bf16.h>
#include <cstdint>

// Problem constants
#define BB 2
#define LL 64
#define DD 1024
#define HH 512
#define SS 50000
#define VV 40000
#define KK 32
#define MM 128            // B*L rows
#define SLM_SCALE 0.1f
#define BN_EPS 1e-5f

// ---------------- scratch (device globals; no allocation allowed) ----------------
__device__ float g_scale[LL];
__device__ float g_shift[LL];
__device__ float g_hpre[8 * MM * HH];      // 8 K-split partials (deterministic, no atomics)
__device__ float g_h[MM * HH];             // relu(h)
__device__ __nv_bfloat16 g_vT[(size_t)VV * MM];  // v transposed, bf16: [col][bl]

// ---------------- packed f32x2 helpers (Blackwell FFMA2) ----------------
__device__ __forceinline__ unsigned long long pack2(float lo, float hi) {
    unsigned long long r;
    asm("mov.b64 %0, {%1, %2};" : "=l"(r) : "f"(lo), "f"(hi));
    return r;
}
__device__ __forceinline__ void unpack2(unsigned long long v, float &lo, float &hi) {
    asm("mov.b64 {%0, %1}, %2;" : "=f"(lo), "=f"(hi) : "l"(v));
}
__device__ __forceinline__ void fma2(unsigned long long &c, unsigned long long a, unsigned long long b) {
    asm("fma.rn.f32x2 %0, %1, %2, %0;" : "+l"(c) : "l"(a), "l"(b));
}

// ---------------- K1: BatchNorm stats per l (over B, D) ----------------
__global__ void k1_stats(const float* __restrict__ x,
                         const float* __restrict__ gamma,
                         const float* __restrict__ beta) {
    __shared__ float redS[8], redQ[8];
    int l = blockIdx.x, t = threadIdx.x;
    float s = 0.f, q = 0.f;
    for (int i = t; i < BB * DD; i += 256) {
        int b = i >> 10, d = i & (DD - 1);
        float v = x[(b * LL + l) * DD + d];
        s += v; q += v * v;
    }
    #pragma unroll
    for (int o = 16; o; o >>= 1) {
        s += __shfl_xor_sync(0xffffffffu, s, o);
        q += __shfl_xor_sync(0xffffffffu, q, o);
    }
    if ((t & 31) == 0) { redS[t >> 5] = s; redQ[t >> 5] = q; }
    __syncthreads();
    if (t == 0) {
        float ss = 0.f, qq = 0.f;
        #pragma unroll
        for (int w = 0; w < 8; w++) { ss += redS[w]; qq += redQ[w]; }
        float mean = ss * (1.f / (BB * DD));
        float var  = qq * (1.f / (BB * DD)) - mean * mean;
        float rstd = rsqrtf(var + BN_EPS);
        float sc = gamma[l] * rstd;
        g_scale[l] = sc;
        g_shift[l] = beta[l] - mean * sc;
    }
}

// ---------------- K2: h_pre partial GEMM  (xn @ W1), split-K over 8 slices ----------------
// grid (8, 2, 8): n-tile 64, m-tile 64, k-slice 128.  64 threads, 8x8 micro-tile.
__global__ void k2_hgemm(const float* __restrict__ x, const float* __restrict__ W1) {
    __shared__ float sA[64 * 20];
    __shared__ float sB[16 * 68];
    int t = threadIdx.x;
    int n0 = blockIdx.x * 64, M0 = blockIdx.y * 64, K0 = blockIdx.z * 128;
    int tx = t & 7, ty = t >> 3;
    float acc[8][8];
    #pragma unroll
    for (int i = 0; i < 8; i++)
        #pragma unroll
        for (int j = 0; j < 8; j++) acc[i][j] = 0.f;

    for (int kb = 0; kb < 128; kb += 16) {
        int k0 = K0 + kb;
        #pragma unroll
        for (int i = 0; i < 4; i++) {
            int lin = t + i * 64;
            int mi = lin >> 2, kq = lin & 3;
            float4 av = *(const float4*)&x[(M0 + mi) * DD + k0 + kq * 4];
            float sc = g_scale[mi], sh = g_shift[mi];   // (M0+mi)&63 == mi
            av.x = av.x * sc + sh; av.y = av.y * sc + sh;
            av.z = av.z * sc + sh; av.w = av.w * sc + sh;
            *(float4*)&sA[mi * 20 + kq * 4] = av;
        }
        #pragma unroll
        for (int i = 0; i < 4; i++) {
            int lin = t + i * 64;
            int r = lin >> 4, c4 = lin & 15;
            *(float4*)&sB[r * 68 + c4 * 4] = *(const float4*)&W1[(k0 + r) * HH + n0 + c4 * 4];
        }
        __syncthreads();
        #pragma unroll
        for (int kk = 0; kk < 16; kk++) {
            float a[8], b[8];
            #pragma unroll
            for (int i = 0; i < 8; i++) a[i] = sA[(ty * 8 + i) * 20 + kk];
            #pragma unroll
            for (int j = 0; j < 8; j++) b[j] = sB[kk * 68 + tx * 8 + j];
            #pragma unroll
            for (int i = 0; i < 8; i++)
                #pragma unroll
                for (int j = 0; j < 8; j++) acc[i][j] = fmaf(a[i], b[j], acc[i][j]);
        }
        __syncthreads();
    }
    float* dst = &g_hpre[blockIdx.z * (MM * HH)];
    #pragma unroll
    for (int i = 0; i < 8; i++)
        #pragma unroll
        for (int j = 0; j < 8; j++)
            dst[(M0 + ty * 8 + i) * HH + n0 + tx * 8 + j] = acc[i][j];
}

// ---------------- K2b: sum partials + bias + relu ----------------
__global__ void k2b_relu(const float* __restrict__ b1) {
    int i = blockIdx.x * 256 + threadIdx.x;        // 65536 total
    float v = b1[i & (HH - 1)];
    #pragma unroll
    for (int p = 0; p < 8; p++) v += g_hpre[p * (MM * HH) + i];
    g_h[i] = fmaxf(v, 0.f);
}

// ---------------- shared 128xN GEMM mainloop (f32x2 packed FMA) ----------------
__device__ __forceinline__ void gemm_128xN(const float* __restrict__ Wm, int Ncols, int n0,
                                           float* sAs, float* sBs,
                                           unsigned long long acc[8][4],
                                           int t, int tx, int ty) {
    const bool full = (n0 + 128 <= Ncols);
    for (int kt = 0; kt < HH; kt += 32) {
        #pragma unroll
        for (int i = 0; i < 4; i++) {
            int lin = t + i * 256;
            int mi = lin >> 3, kq = lin & 7;
            float4 av = *(const float4*)&g_h[mi * HH + kt + kq * 4];
            *(float4*)&sAs[mi * 36 + kq * 4] = av;
        }
        if (full) {
            #pragma unroll
            for (int i = 0; i < 4; i++) {
                int lin = t + i * 256;
                int r = lin >> 5, c4 = lin & 31;
                *(float4*)&sBs[r * 128 + c4 * 4] =
                    *(const float4*)&Wm[(size_t)(kt + r) * Ncols + n0 + c4 * 4];
            }
        } else {
            #pragma unroll
            for (int i = 0; i < 4; i++) {
                int lin = t + i * 256;
                int r = lin >> 5, c4 = lin & 31;
                const float* src = &Wm[(size_t)(kt + r) * Ncols];
                int nb = n0 + c4 * 4;
                float4 bv = make_float4(0.f, 0.f, 0.f, 0.f);
                if (nb + 0 < Ncols) bv.x = src[nb + 0];
                if (nb + 1 < Ncols) bv.y = src[nb + 1];
                if (nb + 2 < Ncols) bv.z = src[nb + 2];
                if (nb + 3 < Ncols) bv.w = src[nb + 3];
                *(float4*)&sBs[r * 128 + c4 * 4] = bv;
            }
        }
        __syncthreads();
        #pragma unroll
        for (int kk = 0; kk < 32; kk++) {
            float a[8];
            #pragma unroll
            for (int i = 0; i < 8; i++) a[i] = sAs[(ty * 8 + i) * 36 + kk];
            const unsigned long long* Bp = (const unsigned long long*)&sBs[kk * 128 + tx * 8];
            unsigned long long b0 = Bp[0], b1v = Bp[1], b2v = Bp[2], b3v = Bp[3];
            #pragma unroll
            for (int i = 0; i < 8; i++) {
                unsigned long long pa = pack2(a[i], a[i]);
                fma2(acc[i][0], pa, b0);
                fma2(acc[i][1], pa, b1v);
                fma2(acc[i][2], pa, b2v);
                fma2(acc[i][3], pa, b3v);
            }
        }
        __syncthreads();
    }
}

// ---------------- K3: v GEMM -> bf16 transposed vT ----------------
__global__ void __launch_bounds__(256, 2)
k3_vgemm(const float* __restrict__ Wslm, const float* __restrict__ bslm) {
    extern __shared__ float smem[];
    float* sAs = smem;
    float* sBs = smem + 4608;
    int t = threadIdx.x, tx = t & 15, ty = t >> 4;
    int n0 = blockIdx.x * 128;
    unsigned long long acc[8][4];
    #pragma unroll
    for (int i = 0; i < 8; i++)
        #pragma unroll
        for (int j = 0; j < 4; j++) acc[i][j] = 0ull;

    gemm_128xN(Wslm, VV, n0, sAs, sBs, acc, t, tx, ty);

    __nv_bfloat16* Cs = (__nv_bfloat16*)(smem + 8704);   // [128][130] bf16
    #pragma unroll
    for (int i = 0; i < 8; i++) {
        int m = ty * 8 + i;
        #pragma unroll
        for (int j4 = 0; j4 < 4; j4++) {
            float v0, v1; unpack2(acc[i][j4], v0, v1);
            int n = n0 + tx * 8 + j4 * 2;
            float r0 = 0.f, r1 = 0.f;
            if (n < VV) { r0 = v0 + bslm[n]; r1 = v1 + bslm[n + 1]; }
            ((__nv_bfloat162*)Cs)[m * 65 + tx * 4 + j4] = __floats2bfloat162_rn(r0, r1);
        }
    }
    __syncthreads();
    #pragma unroll
    for (int ii = 0; ii < 32; ii++) {
        int lin = t + ii * 256;
        int col = lin >> 6, blp = lin & 63;
        int colG = n0 + col;
        if (colG < VV) {
            __nv_bfloat16 lo = Cs[(2 * blp) * 130 + col];
            __nv_bfloat16 hi = Cs[(2 * blp + 1) * 130 + col];
            ((__nv_bfloat162*)g_vT)[(size_t)colG * 64 + blp] = __halves2bfloat162(lo, hi);
        }
    }
}

// ---------------- K4: y GEMM + sparse gather + output ----------------
__global__ void __launch_bounds__(256, 2)
k4_ygemm(const float* __restrict__ W2, const float* __restrict__ b2,
         const float* __restrict__ slw, const int* __restrict__ slidx,
         float* __restrict__ out) {
    extern __shared__ float smem[];
    float* sAs = smem;
    float* sBs = smem + 4608;
    float* sSLM = smem + 8704;                          // [128][129] = slm[bl][s]
    int t = threadIdx.x, tx = t & 15, ty = t >> 4;
    int n0 = blockIdx.x * 128;
    unsigned long long acc[8][4];
    #pragma unroll
    for (int i = 0; i < 8; i++)
        #pragma unroll
        for (int j = 0; j < 4; j++) acc[i][j] = 0ull;

    gemm_128xN(W2, SS, n0, sAs, sBs, acc, t, tx, ty);

    // stage sl_idx / sl_weights for this s-tile (reuse GEMM tile smem)
    int* sIdx = (int*)sAs;
    float* sWt = sBs;
    for (int lin = t; lin < 128 * KK; lin += 256) {
        int sl = lin >> 5, k = lin & 31;
        int sg = n0 + sl;
        if (sg < SS) { sIdx[lin] = slidx[sg * KK + k]; sWt[lin] = slw[sg * KK + k]; }
        else         { sIdx[lin] = 0;                  sWt[lin] = 0.f; }
    }
    __syncthreads();

    // gather: thread handles 2 bl rows (bf16x2), 4 s at a time
    int sQuad = t >> 6, blp = t & 63;
    const __nv_bfloat162* vT2 = (const __nv_bfloat162*)g_vT;
    for (int sg = 0; sg < 32; sg++) {
        int sLocal = sg * 4 + sQuad;
        const int* ip = &sIdx[sLocal * KK];
        const float* wp = &sWt[sLocal * KK];
        float ax = 0.f, ay = 0.f;
        #pragma unroll 8
        for (int k = 0; k < KK; k++) {
            float2 pf = __bfloat1622float2(vT2[(size_t)ip[k] * 64 + blp]);
            float w = wp[k];
            ax = fmaf(w, pf.x, ax);
            ay = fmaf(w, pf.y, ay);
        }
        sSLM[(2 * blp) * 129 + sLocal] = ax;
        sSLM[(2 * blp + 1) * 129 + sLocal] = ay;
    }
    __syncthreads();

    #pragma unroll
    for (int i = 0; i < 8; i++) {
        int m = ty * 8 + i;
        #pragma unroll
        for (int j4 = 0; j4 < 4; j4++) {
            int n = n0 + tx * 8 + j4 * 2;
            if (n < SS) {
                float v0, v1; unpack2(acc[i][j4], v0, v1);
                float r0 = v0 + b2[n]     + SLM_SCALE * sSLM[m * 129 + tx * 8 + j4 * 2];
                float r1 = v1 + b2[n + 1] + SLM_SCALE * sSLM[m * 129 + tx * 8 + j4 * 2 + 1];
                *(float2*)&out[(size_t)m * SS + n] = make_float2(r0, r1);
            }
        }
    }
}

// ---------------- launch ----------------
extern "C" void kernel_launch(void* const* d_in, const int* in_sizes, int n_in,
                              void* d_out, int out_size) {
    const float* x     = (const float*)d_in[0];
    const float* gamma = (const float*)d_in[1];
    const float* beta  = (const float*)d_in[2];
    const float* W1    = (const float*)d_in[3];
    const float* b1    = (const float*)d_in[4];
    const float* W2    = (const float*)d_in[5];
    const float* b2    = (const float*)d_in[6];
    const float* Wslm  = (const float*)d_in[7];
    const float* bslm  = (const float*)d_in[8];
    const float* slw   = (const float*)d_in[9];
    const int*   slidx = (const int*)d_in[10];
    float* out = (float*)d_out;

    static bool attr_done = false;
    if (!attr_done) {
        cudaFuncSetAttribute(k3_vgemm, cudaFuncAttributeMaxDynamicSharedMemorySize, 68096);
        cudaFuncSetAttribute(k4_ygemm, cudaFuncAttributeMaxDynamicSharedMemorySize, 100864);
        attr_done = true;
    }

    k1_stats<<<LL, 256>>>(x, gamma, beta);
    {
        dim3 g(8, 2, 8);
        k2_hgemm<<<g, 64>>>(x, W1);
    }
    k2b_relu<<<256, 256>>>(b1);
    k3_vgemm<<<(VV + 127) / 128, 256, 68096>>>(Wslm, bslm);
    k4_ygemm<<<(SS + 127) / 128, 256, 100864>>>(W2, b2, slw, slidx, out);
}

// round 4
// speedup vs baseline: 1.2564x; 1.2564x over previous
#include <cuda_runtime.h>
#include <cuda_bf16.h>
#include <mma.h>
#include <cstdint>

using namespace nvcuda;

// Problem constants
#define BB 2
#define LL 64
#define DD 1024
#define HH 512
#define SS 50000
#define VV 40000
#define KK 32
#define MM 128            // B*L rows
#define SLM_SCALE 0.1f
#define BN_EPS 1e-5f

// ---------------- scratch (device globals; no allocation allowed) ----------------
__device__ float g_scale[LL];
__device__ float g_shift[LL];
__device__ float g_hpre[8 * MM * HH];            // split-K partials for h GEMM
__device__ float g_h[MM * HH];                   // relu(h), tf32-rounded fp32
__device__ __nv_bfloat16 g_vT[(size_t)VV * MM];  // v transposed bf16: [col][bl]

static __device__ __forceinline__ float to_tf32(float x) {
    float r;
    asm("cvt.rna.tf32.f32 %0, %1;" : "=f"(r) : "f"(x));
    return r;
}
static __device__ __forceinline__ float4 to_tf32_4(float4 v) {
    v.x = to_tf32(v.x); v.y = to_tf32(v.y);
    v.z = to_tf32(v.z); v.w = to_tf32(v.w);
    return v;
}

// ---------------- K1: BatchNorm stats per l (over B, D) ----------------
__global__ void k1_stats(const float* __restrict__ x,
                         const float* __restrict__ gamma,
                         const float* __restrict__ beta) {
    __shared__ float redS[8], redQ[8];
    int l = blockIdx.x, t = threadIdx.x;
    float s = 0.f, q = 0.f;
    for (int i = t; i < BB * DD; i += 256) {
        int b = i >> 10, d = i & (DD - 1);
        float v = x[(b * LL + l) * DD + d];
        s += v; q += v * v;
    }
    #pragma unroll
    for (int o = 16; o; o >>= 1) {
        s += __shfl_xor_sync(0xffffffffu, s, o);
        q += __shfl_xor_sync(0xffffffffu, q, o);
    }
    if ((t & 31) == 0) { redS[t >> 5] = s; redQ[t >> 5] = q; }
    __syncthreads();
    if (t == 0) {
        float ss = 0.f, qq = 0.f;
        #pragma unroll
        for (int w = 0; w < 8; w++) { ss += redS[w]; qq += redQ[w]; }
        float mean = ss * (1.f / (BB * DD));
        float var  = qq * (1.f / (BB * DD)) - mean * mean;
        float rstd = rsqrtf(var + BN_EPS);
        float sc = gamma[l] * rstd;
        g_scale[l] = sc;
        g_shift[l] = beta[l] - mean * sc;
    }
}

// ---------------- K2: h partial GEMM (xn @ W1), split-K 8 (fp32 exact) ----------------
__global__ void k2_hgemm(const float* __restrict__ x, const float* __restrict__ W1) {
    __shared__ float sA[64 * 20];
    __shared__ float sB[16 * 68];
    int t = threadIdx.x;
    int n0 = blockIdx.x * 64, M0 = blockIdx.y * 64, K0 = blockIdx.z * 128;
    int tx = t & 7, ty = t >> 3;
    float acc[8][8];
    #pragma unroll
    for (int i = 0; i < 8; i++)
        #pragma unroll
        for (int j = 0; j < 8; j++) acc[i][j] = 0.f;

    for (int kb = 0; kb < 128; kb += 16) {
        int k0 = K0 + kb;
        #pragma unroll
        for (int i = 0; i < 4; i++) {
            int lin = t + i * 64;
            int mi = lin >> 2, kq = lin & 3;
            float4 av = *(const float4*)&x[(M0 + mi) * DD + k0 + kq * 4];
            float sc = g_scale[mi], sh = g_shift[mi];   // (M0+mi)&63 == mi
            av.x = av.x * sc + sh; av.y = av.y * sc + sh;
            av.z = av.z * sc + sh; av.w = av.w * sc + sh;
            *(float4*)&sA[mi * 20 + kq * 4] = av;
        }
        #pragma unroll
        for (int i = 0; i < 4; i++) {
            int lin = t + i * 64;
            int r = lin >> 4, c4 = lin & 15;
            *(float4*)&sB[r * 68 + c4 * 4] = *(const float4*)&W1[(k0 + r) * HH + n0 + c4 * 4];
        }
        __syncthreads();
        #pragma unroll
        for (int kk = 0; kk < 16; kk++) {
            float a[8], b[8];
            #pragma unroll
            for (int i = 0; i < 8; i++) a[i] = sA[(ty * 8 + i) * 20 + kk];
            #pragma unroll
            for (int j = 0; j < 8; j++) b[j] = sB[kk * 68 + tx * 8 + j];
            #pragma unroll
            for (int i = 0; i < 8; i++)
                #pragma unroll
                for (int j = 0; j < 8; j++) acc[i][j] = fmaf(a[i], b[j], acc[i][j]);
        }
        __syncthreads();
    }
    float* dst = &g_hpre[blockIdx.z * (MM * HH)];
    #pragma unroll
    for (int i = 0; i < 8; i++)
        #pragma unroll
        for (int j = 0; j < 8; j++)
            dst[(M0 + ty * 8 + i) * HH + n0 + tx * 8 + j] = acc[i][j];
}

// ---------------- K2b: reduce partials + bias + relu -> tf32-rounded fp32 ----------------
__global__ void k2b_relu(const float* __restrict__ b1) {
    int i = blockIdx.x * 256 + threadIdx.x;        // 65536 total
    float v = b1[i & (HH - 1)];
    #pragma unroll
    for (int p = 0; p < 8; p++) v += g_hpre[p * (MM * HH) + i];
    g_h[i] = to_tf32(fmaxf(v, 0.f));
}

// ---------------- TF32 wmma mainloop (shared by k3/k4) ----------------
// Computes C[128,128] = A[128,512] @ W[512, n0:n0+128] into wmma accumulators.
// smem layout (floats): sA[2][128][36], sB[2][32][136]
#define LDA 36
#define LDB 136
#define SA_STRIDE (128 * LDA)                 // 4608 floats per buffer
#define SB_STRIDE (32 * LDB)                  // 4352 floats per buffer
#define SB_BASE   (2 * SA_STRIDE)             // 9216
#define MAIN_SMEM_FLOATS (2 * SA_STRIDE + 2 * SB_STRIDE)   // 17920 floats = 71680 B
#define LDC 132

typedef wmma::fragment<wmma::accumulator, 16, 16, 8, float> AccFrag;

static __device__ __forceinline__ void ldgA(int kc, int t, float4 ra[4]) {
    #pragma unroll
    for (int i = 0; i < 4; i++) {
        int lin = t + i * 256;
        int row = lin >> 3, kq = lin & 7;
        ra[i] = *(const float4*)&g_h[row * HH + kc + kq * 4];
    }
}
static __device__ __forceinline__ void ldgB(const float* __restrict__ W, int Ncols,
                                            int n0, int kc, int t, float4 rb[4], bool full) {
    #pragma unroll
    for (int i = 0; i < 4; i++) {
        int lin = t + i * 256;
        int r = lin >> 5, c4 = lin & 31;
        const float* src = &W[(size_t)(kc + r) * Ncols + n0 + c4 * 4];
        if (full) {
            rb[i] = *(const float4*)src;
        } else {
            int nb = n0 + c4 * 4;
            float4 v = make_float4(0.f, 0.f, 0.f, 0.f);
            if (nb + 0 < Ncols) v.x = src[0];
            if (nb + 1 < Ncols) v.y = src[1];
            if (nb + 2 < Ncols) v.z = src[2];
            if (nb + 3 < Ncols) v.w = src[3];
            rb[i] = v;
        }
    }
}
static __device__ __forceinline__ void stsAB(float* sm, int buf, int t,
                                             const float4 ra[4], const float4 rb[4]) {
    float* sA = sm + buf * SA_STRIDE;
    float* sB = sm + SB_BASE + buf * SB_STRIDE;
    #pragma unroll
    for (int i = 0; i < 4; i++) {
        int lin = t + i * 256;
        int row = lin >> 3, kq = lin & 7;
        *(float4*)&sA[row * LDA + kq * 4] = ra[i];   // A already tf32-rounded in g_h
    }
    #pragma unroll
    for (int i = 0; i < 4; i++) {
        int lin = t + i * 256;
        int r = lin >> 5, c4 = lin & 31;
        *(float4*)&sB[r * LDB + c4 * 4] = to_tf32_4(rb[i]);
    }
}

static __device__ __forceinline__ void tc_mainloop(
    const float* __restrict__ W, int Ncols, int n0,
    float* sm, AccFrag c[2][4], int t)
{
    int wid = t >> 5;
    int wm = wid >> 1, wn = wid & 1;                 // warp tile: rows wm*32, cols wn*64
    #pragma unroll
    for (int i = 0; i < 2; i++)
        #pragma unroll
        for (int j = 0; j < 4; j++) wmma::fill_fragment(c[i][j], 0.f);

    const bool full = (n0 + 128 <= Ncols);
    float4 ra[4], rb[4];
    ldgA(0, t, ra);
    ldgB(W, Ncols, n0, 0, t, rb, full);
    stsAB(sm, 0, t, ra, rb);
    __syncthreads();

    for (int ch = 0; ch < 16; ch++) {
        if (ch < 15) {
            ldgA((ch + 1) * 32, t, ra);
            ldgB(W, Ncols, n0, (ch + 1) * 32, t, rb, full);
        }
        const float* sA = sm + (ch & 1) * SA_STRIDE;
        const float* sB = sm + SB_BASE + (ch & 1) * SB_STRIDE;
        #pragma unroll
        for (int ks = 0; ks < 4; ks++) {
            wmma::fragment<wmma::matrix_a, 16, 16, 8, wmma::precision::tf32, wmma::row_major> af[2];
            wmma::fragment<wmma::matrix_b, 16, 16, 8, wmma::precision::tf32, wmma::row_major> bf[4];
            #pragma unroll
            for (int i = 0; i < 2; i++)
                wmma::load_matrix_sync(af[i], sA + (wm * 32 + i * 16) * LDA + ks * 8, LDA);
            #pragma unroll
            for (int j = 0; j < 4; j++)
                wmma::load_matrix_sync(bf[j], sB + (ks * 8) * LDB + wn * 64 + j * 16, LDB);
            #pragma unroll
            for (int i = 0; i < 2; i++)
                #pragma unroll
                for (int j = 0; j < 4; j++)
                    wmma::mma_sync(c[i][j], af[i], bf[j], c[i][j]);
        }
        __syncthreads();
        if (ch < 15) {
            stsAB(sm, (ch + 1) & 1, t, ra, rb);
            __syncthreads();
        }
    }
}

static __device__ __forceinline__ void store_acc(float* sC, AccFrag c[2][4], int t) {
    int wid = t >> 5;
    int wm = wid >> 1, wn = wid & 1;
    #pragma unroll
    for (int i = 0; i < 2; i++)
        #pragma unroll
        for (int j = 0; j < 4; j++)
            wmma::store_matrix_sync(sC + (wm * 32 + i * 16) * LDC + wn * 64 + j * 16,
                                    c[i][j], LDC, wmma::mem_row_major);
}

// ---------------- K3: v GEMM -> bf16 transposed vT ----------------
__global__ void __launch_bounds__(256, 1)
k3_vgemm(const float* __restrict__ Wslm, const float* __restrict__ bslm) {
    extern __shared__ float sm[];
    int t = threadIdx.x;
    int n0 = blockIdx.x * 128;

    AccFrag c[2][4];
    tc_mainloop(Wslm, VV, n0, sm, c, t);
    __syncthreads();                      // smem free; reuse as sC

    float* sC = sm;                       // [128][132]
    store_acc(sC, c, t);
    __syncthreads();

    #pragma unroll
    for (int ii = 0; ii < 32; ii++) {
        int lin = t + ii * 256;
        int col = lin >> 6, blp = lin & 63;
        int colG = n0 + col;
        if (colG < VV) {
            float bias = bslm[colG];
            __nv_bfloat16 lo = __float2bfloat16(sC[(2 * blp) * LDC + col] + bias);
            __nv_bfloat16 hi = __float2bfloat16(sC[(2 * blp + 1) * LDC + col] + bias);
            ((__nv_bfloat162*)g_vT)[(size_t)colG * 64 + blp] = __halves2bfloat162(lo, hi);
        }
    }
}

// ---------------- K4: y GEMM + sparse gather + output ----------------
// epilogue smem: sC [128][132] @0 (67584B), sSLM [128][129] @67584 (66048B),
//                sIdx @133632 (16384B), sWt @150016 (16384B) -> total 166400B
__global__ void __launch_bounds__(256, 1)
k4_ygemm(const float* __restrict__ W2, const float* __restrict__ b2,
         const float* __restrict__ slw, const int* __restrict__ slidx,
         float* __restrict__ out) {
    extern __shared__ float sm[];
    int t = threadIdx.x;
    int n0 = blockIdx.x * 128;

    AccFrag c[2][4];
    tc_mainloop(W2, SS, n0, sm, c, t);
    __syncthreads();

    float* sC   = sm;
    float* sSLM = sm + 16896;             // 67584/4
    int*   sIdx = (int*)(sm + 33408);     // 133632/4
    float* sWt  = sm + 37504;             // 150016/4

    store_acc(sC, c, t);
    for (int lin = t; lin < 128 * KK; lin += 256) {
        int sl = lin >> 5, k = lin & 31;
        int sg = n0 + sl;
        if (sg < SS) { sIdx[lin] = slidx[sg * KK + k]; sWt[lin] = slw[sg * KK + k]; }
        else         { sIdx[lin] = 0;                  sWt[lin] = 0.f; }
    }
    __syncthreads();

    // gather: thread handles 2 bl rows (bf16x2), 4 s at a time
    {
        int sQuad = t >> 6, blp = t & 63;
        const __nv_bfloat162* vT2 = (const __nv_bfloat162*)g_vT;
        for (int sg = 0; sg < 32; sg++) {
            int sLocal = sg * 4 + sQuad;
            const int* ip = &sIdx[sLocal * KK];
            const float* wp = &sWt[sLocal * KK];
            float ax = 0.f, ay = 0.f;
            #pragma unroll 8
            for (int k = 0; k < KK; k++) {
                float2 pf = __bfloat1622float2(vT2[(size_t)ip[k] * 64 + blp]);
                float w = wp[k];
                ax = fmaf(w, pf.x, ax);
                ay = fmaf(w, pf.y, ay);
            }
            sSLM[(2 * blp) * 129 + sLocal] = ax;
            sSLM[(2 * blp + 1) * 129 + sLocal] = ay;
        }
    }
    __syncthreads();

    int nvalid = SS - n0; if (nvalid > 128) nvalid = 128;
    #pragma unroll
    for (int ii = 0; ii < 16; ii++) {
        int lin = t + ii * 256;
        int r = lin >> 5, cq = lin & 31;
        int n = cq * 4;
        if (n < nvalid) {
            float4 cv = *(float4*)&sC[r * LDC + n];
            float4 res;
            res.x = cv.x + b2[n0 + n + 0] + SLM_SCALE * sSLM[r * 129 + n + 0];
            res.y = cv.y + b2[n0 + n + 1] + SLM_SCALE * sSLM[r * 129 + n + 1];
            res.z = cv.z + b2[n0 + n + 2] + SLM_SCALE * sSLM[r * 129 + n + 2];
            res.w = cv.w + b2[n0 + n + 3] + SLM_SCALE * sSLM[r * 129 + n + 3];
            *(float4*)&out[(size_t)r * SS + n0 + n] = res;
        }
    }
}

// ---------------- launch ----------------
extern "C" void kernel_launch(void* const* d_in, const int* in_sizes, int n_in,
                              void* d_out, int out_size) {
    const float* x     = (const float*)d_in[0];
    const float* gamma = (const float*)d_in[1];
    const float* beta  = (const float*)d_in[2];
    const float* W1    = (const float*)d_in[3];
    const float* b1    = (const float*)d_in[4];
    const float* W2    = (const float*)d_in[5];
    const float* b2    = (const float*)d_in[6];
    const float* Wslm  = (const float*)d_in[7];
    const float* bslm  = (const float*)d_in[8];
    const float* slw   = (const float*)d_in[9];
    const int*   slidx = (const int*)d_in[10];
    float* out = (float*)d_out;

    const int SM3 = MAIN_SMEM_FLOATS * 4;   // 71680
    const int SM4 = 166400;

    cudaFuncSetAttribute(k3_vgemm, cudaFuncAttributeMaxDynamicSharedMemorySize, SM3);
    cudaFuncSetAttribute(k4_ygemm, cudaFuncAttributeMaxDynamicSharedMemorySize, SM4);

    k1_stats<<<LL, 256>>>(x, gamma, beta);
    {
        dim3 g(8, 2, 8);
        k2_hgemm<<<g, 64>>>(x, W1);
    }
    k2b_relu<<<256, 256>>>(b1);
    k3_vgemm<<<(VV + 127) / 128, 256, SM3>>>(Wslm, bslm);
    k4_ygemm<<<(SS + 127) / 128, 256, SM4>>>(W2, b2, slw, slidx, out);
}

// round 8
// speedup vs baseline: 1.4035x; 1.1172x over previous
#include <cuda_runtime.h>
#include <cuda_bf16.h>
#include <mma.h>
#include <cstdint>

using namespace nvcuda;

// Problem constants
#define BB 2
#define LL 64
#define DD 1024
#define HH 512
#define SS 50000
#define VV 40000
#define KK 32
#define MM 128            // B*L rows
#define SLM_SCALE 0.1f
#define BN_EPS 1e-5f
// compensation for tf32 RZ truncation of B operands (mean relative bias ~ -0.69*2^-11)
#define COMP 1.000345f

// ---------------- scratch (device globals; no allocation allowed) ----------------
__device__ float g_scale[LL];
__device__ float g_shift[LL];
__device__ float g_hpre[8 * MM * HH];            // split-K partials for h GEMM
__device__ float g_h[MM * HH];                   // relu(h), tf32(RNA)-rounded fp32
__device__ __nv_bfloat16 g_vT[(size_t)VV * MM];  // v transposed bf16: [col][bl]

static __device__ __forceinline__ float to_tf32(float x) {
    float r;
    asm("cvt.rna.tf32.f32 %0, %1;" : "=f"(r) : "f"(x));
    return r;
}

// ---------------- K1: BatchNorm stats per l (over B, D) ----------------
__global__ void k1_stats(const float* __restrict__ x,
                         const float* __restrict__ gamma,
                         const float* __restrict__ beta) {
    __shared__ float redS[8], redQ[8];
    int l = blockIdx.x, t = threadIdx.x;
    float s = 0.f, q = 0.f;
    for (int i = t; i < BB * DD; i += 256) {
        int b = i >> 10, d = i & (DD - 1);
        float v = x[(b * LL + l) * DD + d];
        s += v; q += v * v;
    }
    #pragma unroll
    for (int o = 16; o; o >>= 1) {
        s += __shfl_xor_sync(0xffffffffu, s, o);
        q += __shfl_xor_sync(0xffffffffu, q, o);
    }
    if ((t & 31) == 0) { redS[t >> 5] = s; redQ[t >> 5] = q; }
    __syncthreads();
    if (t == 0) {
        float ss = 0.f, qq = 0.f;
        #pragma unroll
        for (int w = 0; w < 8; w++) { ss += redS[w]; qq += redQ[w]; }
        float mean = ss * (1.f / (BB * DD));
        float var  = qq * (1.f / (BB * DD)) - mean * mean;
        float rstd = rsqrtf(var + BN_EPS);
        float sc = gamma[l] * rstd;
        g_scale[l] = sc;
        g_shift[l] = beta[l] - mean * sc;
    }
}

// ---------------- K2: h partial GEMM (xn @ W1), split-K 8 (fp32 exact) ----------------
__global__ void k2_hgemm(const float* __restrict__ x, const float* __restrict__ W1) {
    __shared__ float sA[64 * 20];
    __shared__ float sB[16 * 68];
    int t = threadIdx.x;
    int n0 = blockIdx.x * 64, M0 = blockIdx.y * 64, K0 = blockIdx.z * 128;
    int tx = t & 7, ty = t >> 3;
    float acc[8][8];
    #pragma unroll
    for (int i = 0; i < 8; i++)
        #pragma unroll
        for (int j = 0; j < 8; j++) acc[i][j] = 0.f;

    for (int kb = 0; kb < 128; kb += 16) {
        int k0 = K0 + kb;
        #pragma unroll
        for (int i = 0; i < 4; i++) {
            int lin = t + i * 64;
            int mi = lin >> 2, kq = lin & 3;
            float4 av = *(const float4*)&x[(M0 + mi) * DD + k0 + kq * 4];
            float sc = g_scale[mi], sh = g_shift[mi];   // (M0+mi)&63 == mi
            av.x = av.x * sc + sh; av.y = av.y * sc + sh;
            av.z = av.z * sc + sh; av.w = av.w * sc + sh;
            *(float4*)&sA[mi * 20 + kq * 4] = av;
        }
        #pragma unroll
        for (int i = 0; i < 4; i++) {
            int lin = t + i * 64;
            int r = lin >> 4, c4 = lin & 15;
            *(float4*)&sB[r * 68 + c4 * 4] = *(const float4*)&W1[(k0 + r) * HH + n0 + c4 * 4];
        }
        __syncthreads();
        #pragma unroll
        for (int kk = 0; kk < 16; kk++) {
            float a[8], b[8];
            #pragma unroll
            for (int i = 0; i < 8; i++) a[i] = sA[(ty * 8 + i) * 20 + kk];
            #pragma unroll
            for (int j = 0; j < 8; j++) b[j] = sB[kk * 68 + tx * 8 + j];
            #pragma unroll
            for (int i = 0; i < 8; i++)
                #pragma unroll
                for (int j = 0; j < 8; j++) acc[i][j] = fmaf(a[i], b[j], acc[i][j]);
        }
        __syncthreads();
    }
    float* dst = &g_hpre[blockIdx.z * (MM * HH)];
    #pragma unroll
    for (int i = 0; i < 8; i++)
        #pragma unroll
        for (int j = 0; j < 8; j++)
            dst[(M0 + ty * 8 + i) * HH + n0 + tx * 8 + j] = acc[i][j];
}

// ---------------- K2b: reduce partials + bias + relu -> tf32(RNA) fp32 ----------------
__global__ void k2b_relu(const float* __restrict__ b1) {
    int i = blockIdx.x * 256 + threadIdx.x;        // 65536 total
    float v = b1[i & (HH - 1)];
    #pragma unroll
    for (int p = 0; p < 8; p++) v += g_hpre[p * (MM * HH) + i];
    g_h[i] = to_tf32(fmaxf(v, 0.f));
}

// ---------------- TF32 wmma mainloop with cp.async 3-stage pipeline ----------------
// 512 threads, CTA tile 128x128, warp tile 32x32 (16 warps).
#define LDA 36
#define LDB 132
#define SA_FLOATS (128 * LDA)                 // 4608
#define SB_FLOATS (32 * LDB)                  // 4224
#define STG_FLOATS (SA_FLOATS + SB_FLOATS)    // 8832 floats = 35328 B / stage
#define NSTAGE 3
#define PIPE_BYTES (NSTAGE * STG_FLOATS * 4)  // 105984
#define LDC 132

typedef wmma::fragment<wmma::accumulator, 16, 16, 8, float> AccFrag;

static __device__ __forceinline__ uint32_t smem_u32(const void* p) {
    return (uint32_t)__cvta_generic_to_shared(p);
}

static __device__ __forceinline__ void issue_stage(
    uint32_t suStage, const float* __restrict__ W, int Ncols, int n0, int kc, int t)
{
    // A: 128 rows x 32 floats (16B x 1024)
    #pragma unroll
    for (int i = 0; i < 2; i++) {
        int lin = t + i * 512;
        int row = lin >> 3, q = lin & 7;
        uint32_t dst = suStage + (uint32_t)(row * LDA + q * 4) * 4u;
        const float* src = &g_h[row * HH + kc + q * 4];
        asm volatile("cp.async.cg.shared.global [%0], [%1], 16;\n" :: "r"(dst), "l"(src));
    }
    // B: 32 rows x 128 floats, zero-fill past Ncols
    #pragma unroll
    for (int i = 0; i < 2; i++) {
        int lin = t + i * 512;
        int r = lin >> 5, c4 = lin & 31;
        uint32_t dst = suStage + (uint32_t)(SA_FLOATS + r * LDB + c4 * 4) * 4u;
        int n = n0 + c4 * 4;
        int rem = Ncols - n;
        int bytes = rem >= 4 ? 16 : (rem > 0 ? rem * 4 : 0);
        const float* src = (rem > 0) ? &W[(size_t)(kc + r) * Ncols + n] : W;
        asm volatile("cp.async.cg.shared.global [%0], [%1], 16, %2;\n"
                     :: "r"(dst), "l"(src), "r"(bytes));
    }
    asm volatile("cp.async.commit_group;\n" ::: "memory");
}

static __device__ __forceinline__ void tc_mainloop(
    const float* __restrict__ W, int Ncols, int n0,
    float* sm, AccFrag c[2][2], int t)
{
    int wid = t >> 5;
    int wm = wid >> 2, wn = wid & 3;   // 4x4 warp grid, 32x32 tiles
    #pragma unroll
    for (int i = 0; i < 2; i++)
        #pragma unroll
        for (int j = 0; j < 2; j++) wmma::fill_fragment(c[i][j], 0.f);

    uint32_t su = smem_u32(sm);
    issue_stage(su + 0 * STG_FLOATS * 4, W, Ncols, n0, 0, t);
    issue_stage(su + 1 * STG_FLOATS * 4, W, Ncols, n0, 32, t);
    issue_stage(su + 2 * STG_FLOATS * 4, W, Ncols, n0, 64, t);

    for (int ch = 0; ch < 16; ch++) {
        if (ch < 14)       asm volatile("cp.async.wait_group 2;\n" ::: "memory");
        else if (ch == 14) asm volatile("cp.async.wait_group 1;\n" ::: "memory");
        else               asm volatile("cp.async.wait_group 0;\n" ::: "memory");
        __syncthreads();

        const float* sA = sm + (ch % 3) * STG_FLOATS;
        const float* sB = sA + SA_FLOATS;
        #pragma unroll
        for (int ks = 0; ks < 4; ks++) {
            wmma::fragment<wmma::matrix_a, 16, 16, 8, wmma::precision::tf32, wmma::row_major> af[2];
            wmma::fragment<wmma::matrix_b, 16, 16, 8, wmma::precision::tf32, wmma::row_major> bf[2];
            #pragma unroll
            for (int i = 0; i < 2; i++)
                wmma::load_matrix_sync(af[i], sA + (wm * 32 + i * 16) * LDA + ks * 8, LDA);
            #pragma unroll
            for (int j = 0; j < 2; j++)
                wmma::load_matrix_sync(bf[j], sB + (ks * 8) * LDB + wn * 32 + j * 16, LDB);
            #pragma unroll
            for (int i = 0; i < 2; i++)
                #pragma unroll
                for (int j = 0; j < 2; j++)
                    wmma::mma_sync(c[i][j], af[i], bf[j], c[i][j]);
        }
        __syncthreads();
        if (ch + 3 < 16)
            issue_stage(su + (ch % 3) * STG_FLOATS * 4, W, Ncols, n0, (ch + 3) * 32, t);
    }
    // compensation for tf32 RZ truncation of B
    #pragma unroll
    for (int i = 0; i < 2; i++)
        #pragma unroll
        for (int j = 0; j < 2; j++)
            #pragma unroll
            for (int e = 0; e < c[i][j].num_elements; e++) c[i][j].x[e] *= COMP;
}

static __device__ __forceinline__ void store_acc(float* sC, AccFrag c[2][2], int t) {
    int wid = t >> 5;
    int wm = wid >> 2, wn = wid & 3;
    #pragma unroll
    for (int i = 0; i < 2; i++)
        #pragma unroll
        for (int j = 0; j < 2; j++)
            wmma::store_matrix_sync(sC + (wm * 32 + i * 16) * LDC + wn * 32 + j * 16,
                                    c[i][j], LDC, wmma::mem_row_major);
}

// ---------------- K3: v GEMM -> bf16 transposed vT ----------------
__global__ void __launch_bounds__(512, 1)
k3_vgemm(const float* __restrict__ Wslm, const float* __restrict__ bslm) {
    extern __shared__ float sm[];
    int t = threadIdx.x;
    int n0 = blockIdx.x * 128;

    AccFrag c[2][2];
    tc_mainloop(Wslm, VV, n0, sm, c, t);
    // last loop iteration ends with __syncthreads(): smem free

    float* sC = sm;                       // [128][132] fp32 = 67584 B
    store_acc(sC, c, t);
    __syncthreads();

    #pragma unroll
    for (int ii = 0; ii < 16; ii++) {
        int lin = t + ii * 512;
        int col = lin >> 6, blp = lin & 63;
        int colG = n0 + col;
        if (colG < VV) {
            float bias = bslm[colG];
            __nv_bfloat16 lo = __float2bfloat16(sC[(2 * blp) * LDC + col] + bias);
            __nv_bfloat16 hi = __float2bfloat16(sC[(2 * blp + 1) * LDC + col] + bias);
            ((__nv_bfloat162*)g_vT)[(size_t)colG * 64 + blp] = __halves2bfloat162(lo, hi);
        }
    }
}

// ---------------- K4: y GEMM + sparse gather + output ----------------
// epilogue smem floats: sC [128][132] @0, sSLM [128][129] @16896,
//                       sIdx @33408, sWt @37504 -> total 41600 floats = 166400 B
__global__ void __launch_bounds__(512, 1)
k4_ygemm(const float* __restrict__ W2, const float* __restrict__ b2,
         const float* __restrict__ slw, const int* __restrict__ slidx,
         float* __restrict__ out) {
    extern __shared__ float sm[];
    int t = threadIdx.x;
    int n0 = blockIdx.x * 128;

    AccFrag c[2][2];
    tc_mainloop(W2, SS, n0, sm, c, t);

    float* sC   = sm;
    float* sSLM = sm + 16896;
    int*   sIdx = (int*)(sm + 33408);
    float* sWt  = sm + 37504;

    store_acc(sC, c, t);
    for (int lin = t; lin < 128 * KK; lin += 512) {
        int sl = lin >> 5, k = lin & 31;
        int sg = n0 + sl;
        if (sg < SS) { sIdx[lin] = slidx[sg * KK + k]; sWt[lin] = slw[sg * KK + k]; }
        else         { sIdx[lin] = 0;                  sWt[lin] = 0.f; }
    }
    __syncthreads();

    // gather: 8 s-octs x 64 bl-pairs; 16 s-groups
    {
        int sOct = t >> 6, blp = t & 63;
        const __nv_bfloat162* vT2 = (const __nv_bfloat162*)g_vT;
        for (int sg = 0; sg < 16; sg++) {
            int sLocal = sg * 8 + sOct;
            const int* ip = &sIdx[sLocal * KK];
            const float* wp = &sWt[sLocal * KK];
            float ax = 0.f, ay = 0.f;
            #pragma unroll 8
            for (int k = 0; k < KK; k++) {
                float2 pf = __bfloat1622float2(vT2[(size_t)ip[k] * 64 + blp]);
                float w = wp[k];
                ax = fmaf(w, pf.x, ax);
                ay = fmaf(w, pf.y, ay);
            }
            sSLM[(2 * blp) * 129 + sLocal] = ax;
            sSLM[(2 * blp + 1) * 129 + sLocal] = ay;
        }
    }
    __syncthreads();

    int nvalid = SS - n0; if (nvalid > 128) nvalid = 128;
    #pragma unroll
    for (int ii = 0; ii < 8; ii++) {
        int lin = t + ii * 512;
        int r = lin >> 5, cq = lin & 31;
        int n = cq * 4;
        if (n < nvalid) {
            float4 cv = *(float4*)&sC[r * LDC + n];
            float4 res;
            res.x = cv.x + b2[n0 + n + 0] + SLM_SCALE * sSLM[r * 129 + n + 0];
            res.y = cv.y + b2[n0 + n + 1] + SLM_SCALE * sSLM[r * 129 + n + 1];
            res.z = cv.z + b2[n0 + n + 2] + SLM_SCALE * sSLM[r * 129 + n + 2];
            res.w = cv.w + b2[n0 + n + 3] + SLM_SCALE * sSLM[r * 129 + n + 3];
            *(float4*)&out[(size_t)r * SS + n0 + n] = res;
        }
    }
}

// ---------------- launch ----------------
extern "C" void kernel_launch(void* const* d_in, const int* in_sizes, int n_in,
                              void* d_out, int out_size) {
    const float* x     = (const float*)d_in[0];
    const float* gamma = (const float*)d_in[1];
    const float* beta  = (const float*)d_in[2];
    const float* W1    = (const float*)d_in[3];
    const float* b1    = (const float*)d_in[4];
    const float* W2    = (const float*)d_in[5];
    const float* b2    = (const float*)d_in[6];
    const float* Wslm  = (const float*)d_in[7];
    const float* bslm  = (const float*)d_in[8];
    const float* slw   = (const float*)d_in[9];
    const int*   slidx = (const int*)d_in[10];
    float* out = (float*)d_out;

    const int SM3 = PIPE_BYTES;             // 105984
    const int SM4 = 166400;                 // epilogue dominates

    cudaFuncSetAttribute(k3_vgemm, cudaFuncAttributeMaxDynamicSharedMemorySize, SM3);
    cudaFuncSetAttribute(k4_ygemm, cudaFuncAttributeMaxDynamicSharedMemorySize, SM4);

    k1_stats<<<LL, 256>>>(x, gamma, beta);
    {
        dim3 g(8, 2, 8);
        k2_hgemm<<<g, 64>>>(x, W1);
    }
    k2b_relu<<<256, 256>>>(b1);
    k3_vgemm<<<(VV + 127) / 128, 512, SM3>>>(Wslm, bslm);
    k4_ygemm<<<(SS + 127) / 128, 512, SM4>>>(W2, b2, slw, slidx, out);
}

// round 10
// speedup vs baseline: 1.5532x; 1.1066x over previous
#include <cuda_runtime.h>
#include <cuda_bf16.h>
#include <mma.h>
#include <cstdint>

using namespace nvcuda;

// Problem constants
#define BB 2
#define LL 64
#define DD 1024
#define HH 512
#define SS 50000
#define VV 40000
#define KK 32
#define MM 128            // B*L rows
#define SLM_SCALE 0.1f
#define BN_EPS 1e-5f
// compensation for tf32 RZ truncation of B operands (mean relative bias ~ -0.69*2^-11)
#define COMP 1.000345f

#define NTILE 64
#define NV_TILES ((VV + NTILE - 1) / NTILE)   // 625
#define NY_TILES ((SS + NTILE - 1) / NTILE)   // 782

// ---------------- scratch (device globals; no allocation allowed) ----------------
__device__ float g_scale[LL];
__device__ float g_shift[LL];
__device__ float g_hpre[8 * MM * HH];            // split-K partials for h GEMM
__device__ float g_h[MM * HH];                   // relu(h), tf32(RNA)-rounded fp32
__device__ __nv_bfloat16 g_vT[(size_t)VV * MM];  // v transposed bf16: [col][bl]

static __device__ __forceinline__ float to_tf32(float x) {
    float r;
    asm("cvt.rna.tf32.f32 %0, %1;" : "=f"(r) : "f"(x));
    return r;
}

// ---------------- K1: BatchNorm stats per l (over B, D) ----------------
__global__ void k1_stats(const float* __restrict__ x,
                         const float* __restrict__ gamma,
                         const float* __restrict__ beta) {
    __shared__ float redS[8], redQ[8];
    int l = blockIdx.x, t = threadIdx.x;
    float s = 0.f, q = 0.f;
    for (int i = t; i < BB * DD; i += 256) {
        int b = i >> 10, d = i & (DD - 1);
        float v = x[(b * LL + l) * DD + d];
        s += v; q += v * v;
    }
    #pragma unroll
    for (int o = 16; o; o >>= 1) {
        s += __shfl_xor_sync(0xffffffffu, s, o);
        q += __shfl_xor_sync(0xffffffffu, q, o);
    }
    if ((t & 31) == 0) { redS[t >> 5] = s; redQ[t >> 5] = q; }
    __syncthreads();
    if (t == 0) {
        float ss = 0.f, qq = 0.f;
        #pragma unroll
        for (int w = 0; w < 8; w++) { ss += redS[w]; qq += redQ[w]; }
        float mean = ss * (1.f / (BB * DD));
        float var  = qq * (1.f / (BB * DD)) - mean * mean;
        float rstd = rsqrtf(var + BN_EPS);
        float sc = gamma[l] * rstd;
        g_scale[l] = sc;
        g_shift[l] = beta[l] - mean * sc;
    }
}

// ---------------- K2: h partial GEMM (xn @ W1), split-K 8 (fp32 exact) ----------------
__global__ void k2_hgemm(const float* __restrict__ x, const float* __restrict__ W1) {
    __shared__ float sA[64 * 20];
    __shared__ float sB[16 * 68];
    int t = threadIdx.x;
    int n0 = blockIdx.x * 64, M0 = blockIdx.y * 64, K0 = blockIdx.z * 128;
    int tx = t & 7, ty = t >> 3;
    float acc[8][8];
    #pragma unroll
    for (int i = 0; i < 8; i++)
        #pragma unroll
        for (int j = 0; j < 8; j++) acc[i][j] = 0.f;

    for (int kb = 0; kb < 128; kb += 16) {
        int k0 = K0 + kb;
        #pragma unroll
        for (int i = 0; i < 4; i++) {
            int lin = t + i * 64;
            int mi = lin >> 2, kq = lin & 3;
            float4 av = *(const float4*)&x[(M0 + mi) * DD + k0 + kq * 4];
            float sc = g_scale[mi], sh = g_shift[mi];   // (M0+mi)&63 == mi
            av.x = av.x * sc + sh; av.y = av.y * sc + sh;
            av.z = av.z * sc + sh; av.w = av.w * sc + sh;
            *(float4*)&sA[mi * 20 + kq * 4] = av;
        }
        #pragma unroll
        for (int i = 0; i < 4; i++) {
            int lin = t + i * 64;
            int r = lin >> 4, c4 = lin & 15;
            *(float4*)&sB[r * 68 + c4 * 4] = *(const float4*)&W1[(k0 + r) * HH + n0 + c4 * 4];
        }
        __syncthreads();
        #pragma unroll
        for (int kk = 0; kk < 16; kk++) {
            float a[8], b[8];
            #pragma unroll
            for (int i = 0; i < 8; i++) a[i] = sA[(ty * 8 + i) * 20 + kk];
            #pragma unroll
            for (int j = 0; j < 8; j++) b[j] = sB[kk * 68 + tx * 8 + j];
            #pragma unroll
            for (int i = 0; i < 8; i++)
                #pragma unroll
                for (int j = 0; j < 8; j++) acc[i][j] = fmaf(a[i], b[j], acc[i][j]);
        }
        __syncthreads();
    }
    float* dst = &g_hpre[blockIdx.z * (MM * HH)];
    #pragma unroll
    for (int i = 0; i < 8; i++)
        #pragma unroll
        for (int j = 0; j < 8; j++)
            dst[(M0 + ty * 8 + i) * HH + n0 + tx * 8 + j] = acc[i][j];
}

// ---------------- K2b: reduce partials + bias + relu -> tf32(RNA) fp32 ----------------
__global__ void k2b_relu(const float* __restrict__ b1) {
    int i = blockIdx.x * 256 + threadIdx.x;        // 65536 total
    float v = b1[i & (HH - 1)];
    #pragma unroll
    for (int p = 0; p < 8; p++) v += g_hpre[p * (MM * HH) + i];
    g_h[i] = to_tf32(fmaxf(v, 0.f));
}

// ---------------- combined TF32 wmma GEMM: 128x64 tile, 4-stage, 1 barrier/chunk ----------------
// 256 threads, 8 warps in 4(m) x 2(n) grid, warp tile 32x32.
#define LDA 36
#define LDB 68
#define SA_FLOATS (128 * LDA)                  // 4608
#define SB_FLOATS (32 * LDB)                   // 2176
#define STG_FLOATS (SA_FLOATS + SB_FLOATS)     // 6784 floats = 27136 B
#define NSTAGE 4
#define PIPE_BYTES (NSTAGE * STG_FLOATS * 4)   // 108544
#define LDC 68

typedef wmma::fragment<wmma::accumulator, 16, 16, 8, float> AccFrag;

static __device__ __forceinline__ uint32_t smem_u32(const void* p) {
    return (uint32_t)__cvta_generic_to_shared(p);
}

static __device__ __forceinline__ void issue_stage(
    uint32_t suStage, const float* __restrict__ W, int Ncols, int n0, int kc, int t)
{
    // A: 128 rows x 32 floats = 1024 x 16B
    #pragma unroll
    for (int i = 0; i < 4; i++) {
        int lin = t + i * 256;
        int row = lin >> 3, q = lin & 7;
        uint32_t dst = suStage + (uint32_t)(row * LDA + q * 4) * 4u;
        const float* src = &g_h[row * HH + kc + q * 4];
        asm volatile("cp.async.cg.shared.global [%0], [%1], 16;\n" :: "r"(dst), "l"(src));
    }
    // B: 32 rows x 64 floats = 512 x 16B, zero-fill past Ncols
    #pragma unroll
    for (int i = 0; i < 2; i++) {
        int lin = t + i * 256;
        int r = lin >> 4, c4 = lin & 15;
        uint32_t dst = suStage + (uint32_t)(SA_FLOATS + r * LDB + c4 * 4) * 4u;
        int n = n0 + c4 * 4;
        int rem = Ncols - n;
        int bytes = rem >= 4 ? 16 : (rem > 0 ? rem * 4 : 0);
        const float* src = (rem > 0) ? &W[(size_t)(kc + r) * Ncols + n] : W;
        asm volatile("cp.async.cg.shared.global [%0], [%1], 16, %2;\n"
                     :: "r"(dst), "l"(src), "r"(bytes));
    }
    asm volatile("cp.async.commit_group;\n" ::: "memory");
}

static __device__ __forceinline__ void tc_mainloop(
    const float* __restrict__ W, int Ncols, int n0,
    float* sm, AccFrag c[2][2], int t)
{
    int wid = t >> 5;
    int wm = wid >> 1, wn = wid & 1;   // 4x2 warp grid, 32x32 tiles
    #pragma unroll
    for (int i = 0; i < 2; i++)
        #pragma unroll
        for (int j = 0; j < 2; j++) wmma::fill_fragment(c[i][j], 0.f);

    uint32_t su = smem_u32(sm);
    issue_stage(su + 0u * STG_FLOATS * 4, W, Ncols, n0, 0, t);
    issue_stage(su + 1u * STG_FLOATS * 4, W, Ncols, n0, 32, t);
    issue_stage(su + 2u * STG_FLOATS * 4, W, Ncols, n0, 64, t);

    for (int ch = 0; ch < 16; ch++) {
        asm volatile("cp.async.wait_group 2;\n" ::: "memory");
        __syncthreads();
        const float* sA = sm + (ch & 3) * STG_FLOATS;
        const float* sB = sA + SA_FLOATS;
        #pragma unroll
        for (int ks = 0; ks < 4; ks++) {
            wmma::fragment<wmma::matrix_a, 16, 16, 8, wmma::precision::tf32, wmma::row_major> af[2];
            wmma::fragment<wmma::matrix_b, 16, 16, 8, wmma::precision::tf32, wmma::row_major> bf[2];
            #pragma unroll
            for (int i = 0; i < 2; i++)
                wmma::load_matrix_sync(af[i], sA + (wm * 32 + i * 16) * LDA + ks * 8, LDA);
            #pragma unroll
            for (int j = 0; j < 2; j++)
                wmma::load_matrix_sync(bf[j], sB + (ks * 8) * LDB + wn * 32 + j * 16, LDB);
            #pragma unroll
            for (int i = 0; i < 2; i++)
                #pragma unroll
                for (int j = 0; j < 2; j++)
                    wmma::mma_sync(c[i][j], af[i], bf[j], c[i][j]);
        }
        // issue into the slot freed by the barrier above (stage ch-1's slot)
        if (ch + 3 < 16) {
            issue_stage(su + (uint32_t)((ch + 3) & 3) * STG_FLOATS * 4, W, Ncols, n0, (ch + 3) * 32, t);
        } else {
            asm volatile("cp.async.commit_group;\n" ::: "memory");   // empty group: keeps wait counts exact
        }
    }
    __syncthreads();   // all MMA reads done before smem reuse
    // compensation for tf32 RZ truncation of B
    #pragma unroll
    for (int i = 0; i < 2; i++)
        #pragma unroll
        for (int j = 0; j < 2; j++)
            #pragma unroll
            for (int e = 0; e < c[i][j].num_elements; e++) c[i][j].x[e] *= COMP;
}

// ---------------- combined GEMM kernel: v tiles then y tiles ----------------
__global__ void __launch_bounds__(256, 2)
kgemm(const float* __restrict__ Wslm, const float* __restrict__ bslm,
      const float* __restrict__ W2,  const float* __restrict__ b2,
      float* __restrict__ out) {
    extern __shared__ float sm[];
    int t = threadIdx.x;
    int bid = blockIdx.x;
    bool isV = bid < NV_TILES;
    int n0 = (isV ? bid : bid - NV_TILES) * NTILE;
    const float* W = isV ? Wslm : W2;
    int Ncols = isV ? VV : SS;

    AccFrag c[2][2];
    tc_mainloop(W, Ncols, n0, sm, c, t);

    float* sC = sm;                        // [128][68]
    {
        int wid = t >> 5;
        int wm = wid >> 1, wn = wid & 1;
        #pragma unroll
        for (int i = 0; i < 2; i++)
            #pragma unroll
            for (int j = 0; j < 2; j++)
                wmma::store_matrix_sync(sC + (wm * 32 + i * 16) * LDC + wn * 32 + j * 16,
                                        c[i][j], LDC, wmma::mem_row_major);
    }
    __syncthreads();

    if (isV) {
        // bias + bf16, transpose-write to g_vT[col][bl pairs]; 64 cols x 64 pairs
        #pragma unroll
        for (int ii = 0; ii < 16; ii++) {
            int lin = t + ii * 256;
            int col = lin >> 6, blp = lin & 63;
            int colG = n0 + col;           // < 40000 always (625*64 exact)
            float bias = bslm[colG];
            __nv_bfloat16 lo = __float2bfloat16(sC[(2 * blp) * LDC + col] + bias);
            __nv_bfloat16 hi = __float2bfloat16(sC[(2 * blp + 1) * LDC + col] + bias);
            ((__nv_bfloat162*)g_vT)[(size_t)colG * 64 + blp] = __halves2bfloat162(lo, hi);
        }
    } else {
        int nvalid = SS - n0; if (nvalid > NTILE) nvalid = NTILE;
        #pragma unroll
        for (int ii = 0; ii < 8; ii++) {
            int lin = t + ii * 256;
            int r = lin >> 4, cq = lin & 15;
            int n = cq * 4;
            if (n < nvalid) {
                float4 cv = *(float4*)&sC[r * LDC + n];
                float4 res;
                res.x = cv.x + b2[n0 + n + 0];
                res.y = cv.y + b2[n0 + n + 1];
                res.z = cv.z + b2[n0 + n + 2];
                res.w = cv.w + b2[n0 + n + 3];
                *(float4*)&out[(size_t)r * SS + n0 + n] = res;
            }
        }
    }
}

// ---------------- K5: sparse gather, RMW out ----------------
// smem floats: sSLM [128][65] @0, sIdx @8320 (2048 ints), sWt @10368 (2048 f)
#define K5_SMEM ((8320 + 2048 + 2048) * 4)     // 49664 B
__global__ void __launch_bounds__(256)
k5_gather(const float* __restrict__ slw, const int* __restrict__ slidx,
          float* __restrict__ out) {
    extern __shared__ float sm[];
    float* sSLM = sm;
    int*   sIdx = (int*)(sm + 8320);
    float* sWt  = sm + 10368;
    int t = threadIdx.x;
    int n0 = blockIdx.x * NTILE;

    #pragma unroll
    for (int ii = 0; ii < 8; ii++) {
        int lin = t + ii * 256;                 // 2048 = 64 s x 32 k
        int sl = lin >> 5, k = lin & 31;
        int sg = n0 + sl;
        if (sg < SS) { sIdx[lin] = slidx[sg * KK + k]; sWt[lin] = slw[sg * KK + k]; }
        else         { sIdx[lin] = 0;                  sWt[lin] = 0.f; }
    }
    __syncthreads();

    {
        int sOct = t >> 6, blp = t & 63;        // 4 s-slots x 64 bl-pairs
        const __nv_bfloat162* vT2 = (const __nv_bfloat162*)g_vT;
        for (int sg = 0; sg < 16; sg++) {
            int sLocal = sg * 4 + sOct;
            const int* ip = &sIdx[sLocal * KK];
            const float* wp = &sWt[sLocal * KK];
            float ax = 0.f, ay = 0.f;
            #pragma unroll 8
            for (int k = 0; k < KK; k++) {
                float2 pf = __bfloat1622float2(vT2[(size_t)ip[k] * 64 + blp]);
                float w = wp[k];
                ax = fmaf(w, pf.x, ax);
                ay = fmaf(w, pf.y, ay);
            }
            sSLM[(2 * blp) * 65 + sLocal] = ax;
            sSLM[(2 * blp + 1) * 65 + sLocal] = ay;
        }
    }
    __syncthreads();

    int nvalid = SS - n0; if (nvalid > NTILE) nvalid = NTILE;
    #pragma unroll
    for (int ii = 0; ii < 8; ii++) {
        int lin = t + ii * 256;
        int r = lin >> 4, cq = lin & 15;
        int n = cq * 4;
        if (n < nvalid) {
            float4 o = *(float4*)&out[(size_t)r * SS + n0 + n];
            o.x += SLM_SCALE * sSLM[r * 65 + n + 0];
            o.y += SLM_SCALE * sSLM[r * 65 + n + 1];
            o.z += SLM_SCALE * sSLM[r * 65 + n + 2];
            o.w += SLM_SCALE * sSLM[r * 65 + n + 3];
            *(float4*)&out[(size_t)r * SS + n0 + n] = o;
        }
    }
}

// ---------------- launch ----------------
extern "C" void kernel_launch(void* const* d_in, const int* in_sizes, int n_in,
                              void* d_out, int out_size) {
    const float* x     = (const float*)d_in[0];
    const float* gamma = (const float*)d_in[1];
    const float* beta  = (const float*)d_in[2];
    const float* W1    = (const float*)d_in[3];
    const float* b1    = (const float*)d_in[4];
    const float* W2    = (const float*)d_in[5];
    const float* b2    = (const float*)d_in[6];
    const float* Wslm  = (const float*)d_in[7];
    const float* bslm  = (const float*)d_in[8];
    const float* slw   = (const float*)d_in[9];
    const int*   slidx = (const int*)d_in[10];
    float* out = (float*)d_out;

    cudaFuncSetAttribute(kgemm, cudaFuncAttributeMaxDynamicSharedMemorySize, PIPE_BYTES);
    cudaFuncSetAttribute(k5_gather, cudaFuncAttributeMaxDynamicSharedMemorySize, K5_SMEM);

    k1_stats<<<LL, 256>>>(x, gamma, beta);
    {
        dim3 g(8, 2, 8);
        k2_hgemm<<<g, 64>>>(x, W1);
    }
    k2b_relu<<<256, 256>>>(b1);
    kgemm<<<NV_TILES + NY_TILES, 256, PIPE_BYTES>>>(Wslm, bslm, W2, b2, out);
    k5_gather<<<NY_TILES, 256, K5_SMEM>>>(slw, slidx, out);
}

// round 11
// speedup vs baseline: 1.7358x; 1.1176x over previous
#include <cuda_runtime.h>
#include <cuda_bf16.h>
#include <mma.h>
#include <cstdint>

using namespace nvcuda;

// Problem constants
#define BB 2
#define LL 64
#define DD 1024
#define HH 512
#define SS 50000
#define VV 40000
#define KK 32
#define MM 128            // B*L rows
#define SLM_SCALE 0.1f
#define BN_EPS 1e-5f
// compensation for tf32 RZ truncation of B operands (mean relative bias ~ -0.69*2^-11)
#define COMP 1.000345f

#define NTILE 64
#define NV_TILES ((VV + NTILE - 1) / NTILE)   // 625
#define NY_TILES ((SS + NTILE - 1) / NTILE)   // 782

// ---------------- scratch (device globals; no allocation allowed) ----------------
__device__ float g_scale[LL];
__device__ float g_shift[LL];
__device__ float g_hpre[8 * MM * HH];            // split-K partials for h GEMM
__device__ float g_h[MM * HH];                   // relu(h), tf32(RNA)-rounded fp32
__device__ __nv_bfloat16 g_vT[(size_t)VV * MM];  // v transposed bf16: [col][bl]

static __device__ __forceinline__ float to_tf32(float x) {
    float r;
    asm("cvt.rna.tf32.f32 %0, %1;" : "=f"(r) : "f"(x));
    return r;
}

// ---------------- K1: BatchNorm stats per l (over B, D) ----------------
__global__ void k1_stats(const float* __restrict__ x,
                         const float* __restrict__ gamma,
                         const float* __restrict__ beta) {
    __shared__ float redS[8], redQ[8];
    int l = blockIdx.x, t = threadIdx.x;
    float s = 0.f, q = 0.f;
    for (int i = t; i < BB * DD; i += 256) {
        int b = i >> 10, d = i & (DD - 1);
        float v = x[(b * LL + l) * DD + d];
        s += v; q += v * v;
    }
    #pragma unroll
    for (int o = 16; o; o >>= 1) {
        s += __shfl_xor_sync(0xffffffffu, s, o);
        q += __shfl_xor_sync(0xffffffffu, q, o);
    }
    if ((t & 31) == 0) { redS[t >> 5] = s; redQ[t >> 5] = q; }
    __syncthreads();
    if (t == 0) {
        float ss = 0.f, qq = 0.f;
        #pragma unroll
        for (int w = 0; w < 8; w++) { ss += redS[w]; qq += redQ[w]; }
        float mean = ss * (1.f / (BB * DD));
        float var  = qq * (1.f / (BB * DD)) - mean * mean;
        float rstd = rsqrtf(var + BN_EPS);
        float sc = gamma[l] * rstd;
        g_scale[l] = sc;
        g_shift[l] = beta[l] - mean * sc;
    }
}

// ---------------- K2: h partial GEMM (xn @ W1), split-K 8 (fp32 exact) ----------------
__global__ void k2_hgemm(const float* __restrict__ x, const float* __restrict__ W1) {
    __shared__ float sA[64 * 20];
    __shared__ float sB[16 * 68];
    int t = threadIdx.x;
    int n0 = blockIdx.x * 64, M0 = blockIdx.y * 64, K0 = blockIdx.z * 128;
    int tx = t & 7, ty = t >> 3;
    float acc[8][8];
    #pragma unroll
    for (int i = 0; i < 8; i++)
        #pragma unroll
        for (int j = 0; j < 8; j++) acc[i][j] = 0.f;

    for (int kb = 0; kb < 128; kb += 16) {
        int k0 = K0 + kb;
        #pragma unroll
        for (int i = 0; i < 4; i++) {
            int lin = t + i * 64;
            int mi = lin >> 2, kq = lin & 3;
            float4 av = *(const float4*)&x[(M0 + mi) * DD + k0 + kq * 4];
            float sc = g_scale[mi], sh = g_shift[mi];   // (M0+mi)&63 == mi
            av.x = av.x * sc + sh; av.y = av.y * sc + sh;
            av.z = av.z * sc + sh; av.w = av.w * sc + sh;
            *(float4*)&sA[mi * 20 + kq * 4] = av;
        }
        #pragma unroll
        for (int i = 0; i < 4; i++) {
            int lin = t + i * 64;
            int r = lin >> 4, c4 = lin & 15;
            *(float4*)&sB[r * 68 + c4 * 4] = *(const float4*)&W1[(k0 + r) * HH + n0 + c4 * 4];
        }
        __syncthreads();
        #pragma unroll
        for (int kk = 0; kk < 16; kk++) {
            float a[8], b[8];
            #pragma unroll
            for (int i = 0; i < 8; i++) a[i] = sA[(ty * 8 + i) * 20 + kk];
            #pragma unroll
            for (int j = 0; j < 8; j++) b[j] = sB[kk * 68 + tx * 8 + j];
            #pragma unroll
            for (int i = 0; i < 8; i++)
                #pragma unroll
                for (int j = 0; j < 8; j++) acc[i][j] = fmaf(a[i], b[j], acc[i][j]);
        }
        __syncthreads();
    }
    float* dst = &g_hpre[blockIdx.z * (MM * HH)];
    #pragma unroll
    for (int i = 0; i < 8; i++)
        #pragma unroll
        for (int j = 0; j < 8; j++)
            dst[(M0 + ty * 8 + i) * HH + n0 + tx * 8 + j] = acc[i][j];
}

// ---------------- K2b: reduce partials + bias + relu -> tf32(RNA) fp32 ----------------
__global__ void k2b_relu(const float* __restrict__ b1) {
    int i = blockIdx.x * 256 + threadIdx.x;        // 65536 total
    float v = b1[i & (HH - 1)];
    #pragma unroll
    for (int p = 0; p < 8; p++) v += g_hpre[p * (MM * HH) + i];
    g_h[i] = to_tf32(fmaxf(v, 0.f));
}

// ---------------- combined TF32 wmma GEMM ----------------
// CTA tile 128x64, 128 threads (4 warps), warp tile 32x64.
// K-chunk 64, 2-stage cp.async pipeline.
#define KCH 64
#define NCHUNK (HH / KCH)                      // 8
#define LDA 68
#define LDB 68
#define SA_FLOATS (128 * LDA)                  // 8704
#define SB_FLOATS (KCH * LDB)                  // 4352
#define STG_FLOATS (SA_FLOATS + SB_FLOATS)     // 13056 floats = 52224 B
#define NSTAGE 2
#define PIPE_BYTES (NSTAGE * STG_FLOATS * 4)   // 104448
#define LDC 68

typedef wmma::fragment<wmma::accumulator, 16, 16, 8, float> AccFrag;

static __device__ __forceinline__ void issue_stage(
    uint32_t suStage, const float* __restrict__ W, int Ncols, int n0, int kc, int t)
{
    // A: 128 rows x 64 floats = 2048 x 16B
    #pragma unroll
    for (int i = 0; i < 16; i++) {
        int lin = t + i * 128;
        int row = lin >> 4, q = lin & 15;
        uint32_t dst = suStage + (uint32_t)(row * LDA + q * 4) * 4u;
        const float* src = &g_h[row * HH + kc + q * 4];
        asm volatile("cp.async.cg.shared.global [%0], [%1], 16;\n" :: "r"(dst), "l"(src));
    }
    // B: 64 k-rows x 64 floats = 1024 x 16B, zero-fill past Ncols
    #pragma unroll
    for (int i = 0; i < 8; i++) {
        int lin = t + i * 128;
        int r = lin >> 4, c4 = lin & 15;
        uint32_t dst = suStage + (uint32_t)(SA_FLOATS + r * LDB + c4 * 4) * 4u;
        int n = n0 + c4 * 4;
        int rem = Ncols - n;
        int bytes = rem >= 4 ? 16 : (rem > 0 ? rem * 4 : 0);
        const float* src = (rem > 0) ? &W[(size_t)(kc + r) * Ncols + n] : W;
        asm volatile("cp.async.cg.shared.global [%0], [%1], 16, %2;\n"
                     :: "r"(dst), "l"(src), "r"(bytes));
    }
    asm volatile("cp.async.commit_group;\n" ::: "memory");
}

static __device__ __forceinline__ void tc_mainloop(
    const float* __restrict__ W, int Ncols, int n0,
    float* sm, AccFrag c[2][4], int t)
{
    int wm = t >> 5;                    // warp row: 32*wm .. 32*wm+31, full N=64 width
    #pragma unroll
    for (int i = 0; i < 2; i++)
        #pragma unroll
        for (int j = 0; j < 4; j++) wmma::fill_fragment(c[i][j], 0.f);

    uint32_t su = (uint32_t)__cvta_generic_to_shared(sm);
    issue_stage(su + 0u * STG_FLOATS * 4, W, Ncols, n0, 0, t);
    issue_stage(su + 1u * STG_FLOATS * 4, W, Ncols, n0, KCH, t);

    for (int ch = 0; ch < NCHUNK; ch++) {
        asm volatile("cp.async.wait_group 1;\n" ::: "memory");
        __syncthreads();
        const float* sA = sm + (ch & 1) * STG_FLOATS;
        const float* sB = sA + SA_FLOATS;
        #pragma unroll
        for (int ks = 0; ks < KCH / 8; ks++) {
            wmma::fragment<wmma::matrix_a, 16, 16, 8, wmma::precision::tf32, wmma::row_major> af[2];
            wmma::fragment<wmma::matrix_b, 16, 16, 8, wmma::precision::tf32, wmma::row_major> bf[4];
            #pragma unroll
            for (int i = 0; i < 2; i++)
                wmma::load_matrix_sync(af[i], sA + (wm * 32 + i * 16) * LDA + ks * 8, LDA);
            #pragma unroll
            for (int j = 0; j < 4; j++)
                wmma::load_matrix_sync(bf[j], sB + (ks * 8) * LDB + j * 16, LDB);
            #pragma unroll
            for (int i = 0; i < 2; i++)
                #pragma unroll
                for (int j = 0; j < 4; j++)
                    wmma::mma_sync(c[i][j], af[i], bf[j], c[i][j]);
        }
        __syncthreads();   // all warps done reading slot (ch&1) before refill
        if (ch + 2 < NCHUNK) {
            issue_stage(su + (uint32_t)(ch & 1) * STG_FLOATS * 4, W, Ncols, n0, (ch + 2) * KCH, t);
        } else {
            asm volatile("cp.async.commit_group;\n" ::: "memory");   // keep group count exact
        }
    }
    // compensation for tf32 RZ truncation of B
    #pragma unroll
    for (int i = 0; i < 2; i++)
        #pragma unroll
        for (int j = 0; j < 4; j++)
            #pragma unroll
            for (int e = 0; e < c[i][j].num_elements; e++) c[i][j].x[e] *= COMP;
}

// ---------------- combined GEMM kernel: v tiles then y tiles ----------------
__global__ void __launch_bounds__(128, 2)
kgemm(const float* __restrict__ Wslm, const float* __restrict__ bslm,
      const float* __restrict__ W2,  const float* __restrict__ b2,
      float* __restrict__ out) {
    extern __shared__ float sm[];
    int t = threadIdx.x;
    int bid = blockIdx.x;
    bool isV = bid < NV_TILES;
    int n0 = (isV ? bid : bid - NV_TILES) * NTILE;
    const float* W = isV ? Wslm : W2;
    int Ncols = isV ? VV : SS;

    AccFrag c[2][4];
    tc_mainloop(W, Ncols, n0, sm, c, t);

    float* sC = sm;                        // [128][68]
    {
        int wm = t >> 5;
        #pragma unroll
        for (int i = 0; i < 2; i++)
            #pragma unroll
            for (int j = 0; j < 4; j++)
                wmma::store_matrix_sync(sC + (wm * 32 + i * 16) * LDC + j * 16,
                                        c[i][j], LDC, wmma::mem_row_major);
    }
    __syncthreads();

    if (isV) {
        // bias + bf16, transpose-write to g_vT[col][bl pairs]; 64 cols x 64 pairs
        #pragma unroll
        for (int ii = 0; ii < 32; ii++) {
            int lin = t + ii * 128;
            int col = lin >> 6, blp = lin & 63;
            int colG = n0 + col;           // < 40000 always (625*64 exact)
            float bias = bslm[colG];
            __nv_bfloat16 lo = __float2bfloat16(sC[(2 * blp) * LDC + col] + bias);
            __nv_bfloat16 hi = __float2bfloat16(sC[(2 * blp + 1) * LDC + col] + bias);
            ((__nv_bfloat162*)g_vT)[(size_t)colG * 64 + blp] = __halves2bfloat162(lo, hi);
        }
    } else {
        int nvalid = SS - n0; if (nvalid > NTILE) nvalid = NTILE;
        #pragma unroll
        for (int ii = 0; ii < 16; ii++) {
            int lin = t + ii * 128;
            int r = lin >> 4, cq = lin & 15;
            int n = cq * 4;
            if (n < nvalid) {
                float4 cv = *(float4*)&sC[r * LDC + n];
                float4 res;
                res.x = cv.x + b2[n0 + n + 0];
                res.y = cv.y + b2[n0 + n + 1];
                res.z = cv.z + b2[n0 + n + 2];
                res.w = cv.w + b2[n0 + n + 3];
                *(float4*)&out[(size_t)r * SS + n0 + n] = res;
            }
        }
    }
}

// ---------------- K5: sparse gather, RMW out ----------------
// warp-per-s, LDG.64 (4 bl values per lane).
// smem floats: sSLM [128][65] @0, sIdx @8320 (2048 ints), sWt @10368 (2048 f)
#define K5_SMEM ((8320 + 2048 + 2048) * 4)     // 49664 B
__global__ void __launch_bounds__(256)
k5_gather(const float* __restrict__ slw, const int* __restrict__ slidx,
          float* __restrict__ out) {
    extern __shared__ float sm[];
    float* sSLM = sm;
    int*   sIdx = (int*)(sm + 8320);
    float* sWt  = sm + 10368;
    int t = threadIdx.x;
    int n0 = blockIdx.x * NTILE;

    #pragma unroll
    for (int ii = 0; ii < 8; ii++) {
        int lin = t + ii * 256;                 // 2048 = 64 s x 32 k
        int sl = lin >> 5, k = lin & 31;
        int sg = n0 + sl;
        if (sg < SS) { sIdx[lin] = slidx[sg * KK + k]; sWt[lin] = slw[sg * KK + k]; }
        else         { sIdx[lin] = 0;                  sWt[lin] = 0.f; }
    }
    __syncthreads();

    {
        int w = t >> 5, lane = t & 31;          // warp-per-s; lane covers bl 4*lane..4*lane+3
        const uint2* vT4 = (const uint2*)g_vT;  // 128 bf16 per row = 32 uint2
        for (int it = 0; it < 8; it++) {
            int sLocal = it * 8 + w;
            const int* ip = &sIdx[sLocal * KK];
            const float* wp = &sWt[sLocal * KK];
            float a0 = 0.f, a1 = 0.f, a2 = 0.f, a3 = 0.f;
            #pragma unroll 8
            for (int k = 0; k < KK; k++) {
                uint2 pv = vT4[(size_t)ip[k] * 32 + lane];
                float wgt = wp[k];
                float2 p0 = __bfloat1622float2(*(__nv_bfloat162*)&pv.x);
                float2 p1 = __bfloat1622float2(*(__nv_bfloat162*)&pv.y);
                a0 = fmaf(wgt, p0.x, a0);
                a1 = fmaf(wgt, p0.y, a1);
                a2 = fmaf(wgt, p1.x, a2);
                a3 = fmaf(wgt, p1.y, a3);
            }
            sSLM[(4 * lane + 0) * 65 + sLocal] = a0;
            sSLM[(4 * lane + 1) * 65 + sLocal] = a1;
            sSLM[(4 * lane + 2) * 65 + sLocal] = a2;
            sSLM[(4 * lane + 3) * 65 + sLocal] = a3;
        }
    }
    __syncthreads();

    int nvalid = SS - n0; if (nvalid > NTILE) nvalid = NTILE;
    #pragma unroll
    for (int ii = 0; ii < 8; ii++) {
        int lin = t + ii * 256;
        int r = lin >> 4, cq = lin & 15;
        int n = cq * 4;
        if (n < nvalid) {
            float4 o = *(float4*)&out[(size_t)r * SS + n0 + n];
            o.x += SLM_SCALE * sSLM[r * 65 + n + 0];
            o.y += SLM_SCALE * sSLM[r * 65 + n + 1];
            o.z += SLM_SCALE * sSLM[r * 65 + n + 2];
            o.w += SLM_SCALE * sSLM[r * 65 + n + 3];
            *(float4*)&out[(size_t)r * SS + n0 + n] = o;
        }
    }
}

// ---------------- launch ----------------
extern "C" void kernel_launch(void* const* d_in, const int* in_sizes, int n_in,
                              void* d_out, int out_size) {
    const float* x     = (const float*)d_in[0];
    const float* gamma = (const float*)d_in[1];
    const float* beta  = (const float*)d_in[2];
    const float* W1    = (const float*)d_in[3];
    const float* b1    = (const float*)d_in[4];
    const float* W2    = (const float*)d_in[5];
    const float* b2    = (const float*)d_in[6];
    const float* Wslm  = (const float*)d_in[7];
    const float* bslm  = (const float*)d_in[8];
    const float* slw   = (const float*)d_in[9];
    const int*   slidx = (const int*)d_in[10];
    float* out = (float*)d_out;

    cudaFuncSetAttribute(kgemm, cudaFuncAttributeMaxDynamicSharedMemorySize, PIPE_BYTES);
    cudaFuncSetAttribute(k5_gather, cudaFuncAttributeMaxDynamicSharedMemorySize, K5_SMEM);

    k1_stats<<<LL, 256>>>(x, gamma, beta);
    {
        dim3 g(8, 2, 8);
        k2_hgemm<<<g, 64>>>(x, W1);
    }
    k2b_relu<<<256, 256>>>(b1);
    kgemm<<<NV_TILES + NY_TILES, 128, PIPE_BYTES>>>(Wslm, bslm, W2, b2, out);
    k5_gather<<<NY_TILES, 256, K5_SMEM>>>(slw, slidx, out);
}

// round 15
// speedup vs baseline: 2.9036x; 1.6727x over previous
#include <cuda_runtime.h>
#include <cuda_bf16.h>
#include <cuda_fp16.h>
#include <mma.h>
#include <cstdint>

using namespace nvcuda;

// Problem constants
#define BB 2
#define LL 64
#define DD 1024
#define HH 512
#define SS 50000
#define VV 40000
#define KK 32
#define MM 128            // B*L rows
#define SLM_SCALE 0.1f
#define BN_EPS 1e-5f

#define NTILE 64
#define NV_TILES ((VV + NTILE - 1) / NTILE)   // 625
#define NY_TILES ((SS + NTILE - 1) / NTILE)   // 782

// ---------------- scratch (device globals; no allocation allowed) ----------------
__device__ float g_scale[LL];
__device__ float g_shift[LL];
__device__ float g_hpre[8 * MM * HH];            // split-K partials for h GEMM
__device__ __half g_h16[MM * HH];                // relu(h), fp16
__device__ __nv_bfloat16 g_vT[(size_t)VV * MM];  // v transposed bf16: [col][bl]

// ---------------- K1: BatchNorm stats per l (over B, D) ----------------
__global__ void k1_stats(const float* __restrict__ x,
                         const float* __restrict__ gamma,
                         const float* __restrict__ beta) {
    __shared__ float redS[8], redQ[8];
    int l = blockIdx.x, t = threadIdx.x;
    float s = 0.f, q = 0.f;
    for (int i = t; i < BB * DD; i += 256) {
        int b = i >> 10, d = i & (DD - 1);
        float v = x[(b * LL + l) * DD + d];
        s += v; q += v * v;
    }
    #pragma unroll
    for (int o = 16; o; o >>= 1) {
        s += __shfl_xor_sync(0xffffffffu, s, o);
        q += __shfl_xor_sync(0xffffffffu, q, o);
    }
    if ((t & 31) == 0) { redS[t >> 5] = s; redQ[t >> 5] = q; }
    __syncthreads();
    if (t == 0) {
        float ss = 0.f, qq = 0.f;
        #pragma unroll
        for (int w = 0; w < 8; w++) { ss += redS[w]; qq += redQ[w]; }
        float mean = ss * (1.f / (BB * DD));
        float var  = qq * (1.f / (BB * DD)) - mean * mean;
        float rstd = rsqrtf(var + BN_EPS);
        float sc = gamma[l] * rstd;
        g_scale[l] = sc;
        g_shift[l] = beta[l] - mean * sc;
    }
}

// ---------------- K2: h partial GEMM (xn @ W1), split-K 8 (fp32 exact) ----------------
__global__ void k2_hgemm(const float* __restrict__ x, const float* __restrict__ W1) {
    __shared__ float sA[64 * 20];
    __shared__ float sB[16 * 68];
    int t = threadIdx.x;
    int n0 = blockIdx.x * 64, M0 = blockIdx.y * 64, K0 = blockIdx.z * 128;
    int tx = t & 7, ty = t >> 3;
    float acc[8][8];
    #pragma unroll
    for (int i = 0; i < 8; i++)
        #pragma unroll
        for (int j = 0; j < 8; j++) acc[i][j] = 0.f;

    for (int kb = 0; kb < 128; kb += 16) {
        int k0 = K0 + kb;
        #pragma unroll
        for (int i = 0; i < 4; i++) {
            int lin = t + i * 64;
            int mi = lin >> 2, kq = lin & 3;
            float4 av = *(const float4*)&x[(M0 + mi) * DD + k0 + kq * 4];
            float sc = g_scale[mi], sh = g_shift[mi];   // (M0+mi)&63 == mi
            av.x = av.x * sc + sh; av.y = av.y * sc + sh;
            av.z = av.z * sc + sh; av.w = av.w * sc + sh;
            *(float4*)&sA[mi * 20 + kq * 4] = av;
        }
        #pragma unroll
        for (int i = 0; i < 4; i++) {
            int lin = t + i * 64;
            int r = lin >> 4, c4 = lin & 15;
            *(float4*)&sB[r * 68 + c4 * 4] = *(const float4*)&W1[(k0 + r) * HH + n0 + c4 * 4];
        }
        __syncthreads();
        #pragma unroll
        for (int kk = 0; kk < 16; kk++) {
            float a[8], b[8];
            #pragma unroll
            for (int i = 0; i < 8; i++) a[i] = sA[(ty * 8 + i) * 20 + kk];
            #pragma unroll
            for (int j = 0; j < 8; j++) b[j] = sB[kk * 68 + tx * 8 + j];
            #pragma unroll
            for (int i = 0; i < 8; i++)
                #pragma unroll
                for (int j = 0; j < 8; j++) acc[i][j] = fmaf(a[i], b[j], acc[i][j]);
        }
        __syncthreads();
    }
    float* dst = &g_hpre[blockIdx.z * (MM * HH)];
    #pragma unroll
    for (int i = 0; i < 8; i++)
        #pragma unroll
        for (int j = 0; j < 8; j++)
            dst[(M0 + ty * 8 + i) * HH + n0 + tx * 8 + j] = acc[i][j];
}

// ---------------- K2b: reduce partials + bias + relu -> fp16 ----------------
__global__ void k2b_relu(const float* __restrict__ b1) {
    int i = blockIdx.x * 256 + threadIdx.x;        // 65536 total
    float v = b1[i & (HH - 1)];
    #pragma unroll
    for (int p = 0; p < 8; p++) v += g_hpre[p * (MM * HH) + i];
    g_h16[i] = __float2half_rn(fmaxf(v, 0.f));
}

// ---------------- combined FP16 wmma GEMM ----------------
// CTA tile 128x64, 256 threads, warp grid 4(m) x 2(n), warp tile 32x32.
// K-chunk 64, 2-stage cp.async pipeline; B converted fp32->fp16 in smem.
#define KCH 64
#define NCHUNK (HH / KCH)                      // 8
#define LDAH 72                                // halves; 144B row stride
#define LDB  68                                // floats; fp32 B stage
#define LDBH 72                                // halves; fp16 B tile
#define A16_BYTES (128 * LDAH * 2)             // 18432
#define B32_BYTES (KCH * LDB * 4)              // 17408
#define STG_BYTES (A16_BYTES + B32_BYTES)      // 35840
#define OFF_B32   A16_BYTES
#define B16_BYTES (KCH * LDBH * 2)             // 9216
#define OFF_B16   (2 * STG_BYTES)              // 71680
#define PIPE_BYTES (OFF_B16 + 2 * B16_BYTES)   // 90112
#define LDC 68

typedef wmma::fragment<wmma::accumulator, 16, 16, 16, float> AccFrag;

static __device__ __forceinline__ void issue_stage(
    uint32_t suStage, const float* __restrict__ W, int Ncols, int n0, int kc, int t)
{
    // A: 128 rows x 64 halves = 128B/row = 1024 x 16B
    #pragma unroll
    for (int i = 0; i < 4; i++) {
        int lin = t + i * 256;
        int row = lin >> 3, q = lin & 7;
        uint32_t dst = suStage + (uint32_t)(row * LDAH + q * 8) * 2u;
        const __half* src = &g_h16[row * HH + kc + q * 8];
        asm volatile("cp.async.ca.shared.global [%0], [%1], 16;\n" :: "r"(dst), "l"(src));
    }
    // B: 64 k-rows x 64 floats = 1024 x 16B, zero-fill past Ncols
    #pragma unroll
    for (int i = 0; i < 4; i++) {
        int lin = t + i * 256;
        int r = lin >> 4, c4 = lin & 15;
        uint32_t dst = suStage + OFF_B32 + (uint32_t)(r * LDB + c4 * 4) * 4u;
        int n = n0 + c4 * 4;
        int rem = Ncols - n;
        int bytes = rem >= 4 ? 16 : (rem > 0 ? rem * 4 : 0);
        const float* src = (rem > 0) ? &W[(size_t)(kc + r) * Ncols + n] : W;
        asm volatile("cp.async.cg.shared.global [%0], [%1], 16, %2;\n"
                     :: "r"(dst), "l"(src), "r"(bytes));
    }
    asm volatile("cp.async.commit_group;\n" ::: "memory");
}

static __device__ __forceinline__ void tc_mainloop(
    const float* __restrict__ W, int Ncols, int n0,
    char* smc, AccFrag c[2][2], int t)
{
    int wid = t >> 5;
    int wm = wid >> 1, wn = wid & 1;   // 4x2 warp grid, 32x32 tiles
    #pragma unroll
    for (int i = 0; i < 2; i++)
        #pragma unroll
        for (int j = 0; j < 2; j++) wmma::fill_fragment(c[i][j], 0.f);

    uint32_t su = (uint32_t)__cvta_generic_to_shared(smc);
    issue_stage(su + 0u * STG_BYTES, W, Ncols, n0, 0, t);
    issue_stage(su + 1u * STG_BYTES, W, Ncols, n0, KCH, t);

    for (int ch = 0; ch < NCHUNK; ch++) {
        int st = ch & 1;
        asm volatile("cp.async.wait_group 1;\n" ::: "memory");
        __syncthreads();
        // convert B fp32 stage -> fp16 tile (4096 elems; thread t: row t>>2, 16 cols)
        {
            const float* b32 = (const float*)(smc + st * STG_BYTES + OFF_B32);
            __half* b16 = (__half*)(smc + OFF_B16 + st * B16_BYTES);
            int row = t >> 2, cb = (t & 3) * 16;
            const float4* s4 = (const float4*)&b32[row * LDB + cb];
            __half2 h2[8];
            #pragma unroll
            for (int u = 0; u < 4; u++) {
                float4 v = s4[u];
                h2[2 * u]     = __floats2half2_rn(v.x, v.y);
                h2[2 * u + 1] = __floats2half2_rn(v.z, v.w);
            }
            *(uint4*)&b16[row * LDBH + cb]     = *(uint4*)&h2[0];
            *(uint4*)&b16[row * LDBH + cb + 8] = *(uint4*)&h2[4];
        }
        __syncthreads();

        const __half* sA = (const __half*)(smc + st * STG_BYTES);
        const __half* sB = (const __half*)(smc + OFF_B16 + st * B16_BYTES);
        #pragma unroll
        for (int ks = 0; ks < KCH / 16; ks++) {
            wmma::fragment<wmma::matrix_a, 16, 16, 16, __half, wmma::row_major> af[2];
            wmma::fragment<wmma::matrix_b, 16, 16, 16, __half, wmma::row_major> bf[2];
            #pragma unroll
            for (int i = 0; i < 2; i++)
                wmma::load_matrix_sync(af[i], sA + (wm * 32 + i * 16) * LDAH + ks * 16, LDAH);
            #pragma unroll
            for (int j = 0; j < 2; j++)
                wmma::load_matrix_sync(bf[j], sB + (ks * 16) * LDBH + wn * 32 + j * 16, LDBH);
            #pragma unroll
            for (int i = 0; i < 2; i++)
                #pragma unroll
                for (int j = 0; j < 2; j++)
                    wmma::mma_sync(c[i][j], af[i], bf[j], c[i][j]);
        }
        __syncthreads();   // all warps done reading stage st before refill
        if (ch + 2 < NCHUNK) {
            issue_stage(su + (uint32_t)st * STG_BYTES, W, Ncols, n0, (ch + 2) * KCH, t);
        } else {
            asm volatile("cp.async.commit_group;\n" ::: "memory");   // keep group count exact
        }
    }
}

// ---------------- combined GEMM kernel: v tiles then y tiles ----------------
__global__ void __launch_bounds__(256, 2)
kgemm(const float* __restrict__ Wslm, const float* __restrict__ bslm,
      const float* __restrict__ W2,  const float* __restrict__ b2,
      float* __restrict__ out) {
    extern __shared__ char smc[];
    int t = threadIdx.x;
    int bid = blockIdx.x;
    bool isV = bid < NV_TILES;
    int n0 = (isV ? bid : bid - NV_TILES) * NTILE;
    const float* W = isV ? Wslm : W2;
    int Ncols = isV ? VV : SS;

    AccFrag c[2][2];
    tc_mainloop(W, Ncols, n0, smc, c, t);

    float* sC = (float*)smc;               // [128][68] = 34816 B, smem free after mainloop
    {
        int wid = t >> 5;
        int wm = wid >> 1, wn = wid & 1;
        #pragma unroll
        for (int i = 0; i < 2; i++)
            #pragma unroll
            for (int j = 0; j < 2; j++)
                wmma::store_matrix_sync(sC + (wm * 32 + i * 16) * LDC + wn * 32 + j * 16,
                                        c[i][j], LDC, wmma::mem_row_major);
    }
    __syncthreads();

    if (isV) {
        // bias + bf16, transpose-write to g_vT[col][bl pairs]; 64 cols x 64 pairs
        #pragma unroll
        for (int ii = 0; ii < 16; ii++) {
            int lin = t + ii * 256;
            int col = lin >> 6, blp = lin & 63;
            int colG = n0 + col;           // < 40000 always (625*64 exact)
            float bias = bslm[colG];
            __nv_bfloat16 lo = __float2bfloat16(sC[(2 * blp) * LDC + col] + bias);
            __nv_bfloat16 hi = __float2bfloat16(sC[(2 * blp + 1) * LDC + col] + bias);
            ((__nv_bfloat162*)g_vT)[(size_t)colG * 64 + blp] = __halves2bfloat162(lo, hi);
        }
    } else {
        int nvalid = SS - n0; if (nvalid > NTILE) nvalid = NTILE;
        #pragma unroll
        for (int ii = 0; ii < 8; ii++) {
            int lin = t + ii * 256;
            int r = lin >> 4, cq = lin & 15;
            int n = cq * 4;
            if (n < nvalid) {
                float4 cv = *(float4*)&sC[r * LDC + n];
                float4 res;
                res.x = cv.x + b2[n0 + n + 0];
                res.y = cv.y + b2[n0 + n + 1];
                res.z = cv.z + b2[n0 + n + 2];
                res.w = cv.w + b2[n0 + n + 3];
                *(float4*)&out[(size_t)r * SS + n0 + n] = res;
            }
        }
    }
}

// ---------------- K5: sparse gather, RMW out ----------------
// warp-per-s, LDG.64 (4 bl values per lane).
// smem floats: sSLM [128][65] @0, sIdx @8320 (2048 ints), sWt @10368 (2048 f)
#define K5_SMEM ((8320 + 2048 + 2048) * 4)     // 49664 B
__global__ void __launch_bounds__(256)
k5_gather(const float* __restrict__ slw, const int* __restrict__ slidx,
          float* __restrict__ out) {
    extern __shared__ float sm[];
    float* sSLM = sm;
    int*   sIdx = (int*)(sm + 8320);
    float* sWt  = sm + 10368;
    int t = threadIdx.x;
    int n0 = blockIdx.x * NTILE;

    #pragma unroll
    for (int ii = 0; ii < 8; ii++) {
        int lin = t + ii * 256;                 // 2048 = 64 s x 32 k
        int sl = lin >> 5, k = lin & 31;
        int sg = n0 + sl;
        if (sg < SS) { sIdx[lin] = slidx[sg * KK + k]; sWt[lin] = slw[sg * KK + k]; }
        else         { sIdx[lin] = 0;                  sWt[lin] = 0.f; }
    }
    __syncthreads();

    {
        int w = t >> 5, lane = t & 31;          // warp-per-s; lane covers bl 4*lane..4*lane+3
        const uint2* vT4 = (const uint2*)g_vT;  // 128 bf16 per row = 32 uint2
        for (int it = 0; it < 8; it++) {
            int sLocal = it * 8 + w;
            const int* ip = &sIdx[sLocal * KK];
            const float* wp = &sWt[sLocal * KK];
            float a0 = 0.f, a1 = 0.f, a2 = 0.f, a3 = 0.f;
            #pragma unroll 8
            for (int k = 0; k < KK; k++) {
                uint2 pv = vT4[(size_t)ip[k] * 32 + lane];
                float wgt = wp[k];
                float2 p0 = __bfloat1622float2(*(__nv_bfloat162*)&pv.x);
                float2 p1 = __bfloat1622float2(*(__nv_bfloat162*)&pv.y);
                a0 = fmaf(wgt, p0.x, a0);
                a1 = fmaf(wgt, p0.y, a1);
                a2 = fmaf(wgt, p1.x, a2);
                a3 = fmaf(wgt, p1.y, a3);
            }
            sSLM[(4 * lane + 0) * 65 + sLocal] = a0;
            sSLM[(4 * lane + 1) * 65 + sLocal] = a1;
            sSLM[(4 * lane + 2) * 65 + sLocal] = a2;
            sSLM[(4 * lane + 3) * 65 + sLocal] = a3;
        }
    }
    __syncthreads();

    int nvalid = SS - n0; if (nvalid > NTILE) nvalid = NTILE;
    #pragma unroll
    for (int ii = 0; ii < 8; ii++) {
        int lin = t + ii * 256;
        int r = lin >> 4, cq = lin & 15;
        int n = cq * 4;
        if (n < nvalid) {
            float4 o = *(float4*)&out[(size_t)r * SS + n0 + n];
            o.x += SLM_SCALE * sSLM[r * 65 + n + 0];
            o.y += SLM_SCALE * sSLM[r * 65 + n + 1];
            o.z += SLM_SCALE * sSLM[r * 65 + n + 2];
            o.w += SLM_SCALE * sSLM[r * 65 + n + 3];
            *(float4*)&out[(size_t)r * SS + n0 + n] = o;
        }
    }
}

// ---------------- launch ----------------
extern "C" void kernel_launch(void* const* d_in, const int* in_sizes, int n_in,
                              void* d_out, int out_size) {
    const float* x     = (const float*)d_in[0];
    const float* gamma = (const float*)d_in[1];
    const float* beta  = (const float*)d_in[2];
    const float* W1    = (const float*)d_in[3];
    const float* b1    = (const float*)d_in[4];
    const float* W2    = (const float*)d_in[5];
    const float* b2    = (const float*)d_in[6];
    const float* Wslm  = (const float*)d_in[7];
    const float* bslm  = (const float*)d_in[8];
    const float* slw   = (const float*)d_in[9];
    const int*   slidx = (const int*)d_in[10];
    float* out = (float*)d_out;

    cudaFuncSetAttribute(kgemm, cudaFuncAttributeMaxDynamicSharedMemorySize, PIPE_BYTES);
    cudaFuncSetAttribute(k5_gather, cudaFuncAttributeMaxDynamicSharedMemorySize, K5_SMEM);

    k1_stats<<<LL, 256>>>(x, gamma, beta);
    {
        dim3 g(8, 2, 8);
        k2_hgemm<<<g, 64>>>(x, W1);
    }
    k2b_relu<<<256, 256>>>(b1);
    kgemm<<<NV_TILES + NY_TILES, 256, PIPE_BYTES>>>(Wslm, bslm, W2, b2, out);
    k5_gather<<<NY_TILES, 256, K5_SMEM>>>(slw, slidx, out);
}